// round 9
// baseline (speedup 1.0000x reference)
#include <cuda_runtime.h>
#include <cstdint>

#define NN 50000
#define EE 400000
#define H1 256
#define H2 128

// ---- scratch layout (floats) ----
#define OFF_INC1   0                       // N*256
#define OFF_OUT1   12800000                // N*256
#define OFF_INC2   25600000                // N*128
#define OFF_OUT2   32000000                // N*128
#define OFF_E1SUM  38400000                // 256
#define OFF_E2SUM  38400256                // 128
#define OFF_N1SUM  38400384                // 256
#define OFF_N2SUM  38400640                // 128
#define OFF_INVIN  38400768                // N
#define OFF_INVOUT 38450768                // N
#define SCR_TOTAL  38500864
#define ZERO_FLOATS 38400768               // [0, OFF_INVIN) must be zeroed

__device__ float g_scr[SCR_TOTAL];
__device__ int   g_cnt[2 * NN];

typedef unsigned long long ull;

__device__ __forceinline__ void red4(float* p, float a, float b, float c, float d) {
    asm volatile("red.global.add.v4.f32 [%0], {%1,%2,%3,%4};"
                 :: "l"(p), "f"(a), "f"(b), "f"(c), "f"(d) : "memory");
}
__device__ __forceinline__ ull pk2(float x) {
    ull r; asm("mov.b64 %0, {%1, %1};" : "=l"(r) : "f"(x)); return r;
}
__device__ __forceinline__ void ffma2(ull& acc, ull a, ull b) {
    asm("fma.rn.f32x2 %0, %1, %2, %0;" : "+l"(acc) : "l"(a), "l"(b));
}
__device__ __forceinline__ float2 up2(ull v) {
    float2 f; asm("mov.b64 {%0, %1}, %2;" : "=f"(f.x), "=f"(f.y) : "l"(v)); return f;
}
__device__ __forceinline__ uint32_t s2u(const void* p) {
    return (uint32_t)__cvta_generic_to_shared(p);
}
__device__ __forceinline__ void cpa16(uint32_t dst, const void* src) {
    asm volatile("cp.async.cg.shared.global [%0], [%1], 16;" :: "r"(dst), "l"(src));
}
__device__ __forceinline__ void cpa16z(uint32_t dst, const void* src, int ok) {
    asm volatile("cp.async.cg.shared.global [%0], [%1], 16, %2;"
                 :: "r"(dst), "l"(src), "r"(ok ? 16 : 0));
}
#define CPA_COMMIT() asm volatile("cp.async.commit_group;" ::: "memory")
#define CPA_WAIT1()  asm volatile("cp.async.wait_group 1;" ::: "memory")
#define CPA_WAIT0()  asm volatile("cp.async.wait_group 0;" ::: "memory")

// ---------------- zero scratch ----------------
__global__ void k_zero() {
    long i = (long)blockIdx.x * 256 + threadIdx.x;
    if (i < ZERO_FLOATS / 4) {
        float4 z = {0.f, 0.f, 0.f, 0.f};
        *(float4*)(g_scr + i * 4) = z;
    }
    if (i < (2 * NN) / 4) {
        int4 z = {0, 0, 0, 0};
        *(int4*)(g_cnt + i * 4) = z;
    }
}

// ---------------- degrees ----------------
__global__ void k_deg(const int* __restrict__ snd, const int* __restrict__ rcv) {
    int i = blockIdx.x * 256 + threadIdx.x;
    if (i < EE) {
        atomicAdd(&g_cnt[rcv[i]], 1);
        atomicAdd(&g_cnt[NN + snd[i]], 1);
    }
}

__global__ void k_inv() {
    int i = blockIdx.x * 256 + threadIdx.x;
    if (i < NN) {
        int ci = g_cnt[i];      g_scr[OFF_INVIN  + i] = 1.0f / (float)(ci > 1 ? ci : 1);
        int co = g_cnt[NN + i]; g_scr[OFF_INVOUT + i] = 1.0f / (float)(co > 1 ? co : 1);
    }
}

// ---------------- fused edge kernel (12 warps, 8 rows/warp) ----------------
// Scatter contributions are pre-scaled by the target node's inverse degree,
// so inc/out buffers directly hold segment MEANS (k_nodes does no scaling).
#define GRPS 50000   /* EE / 8 */
#define NWARP 12
#define NT 384
__global__ void __launch_bounds__(NT, 1) k_edges(
    const float* __restrict__ edges, const int* __restrict__ snd, const int* __restrict__ rcv,
    const float* __restrict__ We1, const float* __restrict__ be1,
    const float* __restrict__ We2, const float* __restrict__ be2,
    float* __restrict__ e2_out)
{
    extern __shared__ float sm[];
    float* sWe2 = sm;                 // 256*128 = 32768
    float* sWe1 = sWe2 + 32768;       // 16*256  = 4096
    float* sE1  = sWe1 + 4096;        // 12 warps * 8*128 = 12288
    float* sX   = sE1 + 12288;        // 12 warps * 8*16  = 1536
    float* sbe1 = sX + 1536;          // 256
    float* sbe2 = sbe1 + 256;         // 128

    const int tid = threadIdx.x;
    for (int i = tid; i < 32768; i += NT) sWe2[i] = We2[i];
    for (int i = tid; i < 4096;  i += NT) sWe1[i] = We1[i];
    if (tid < 256) sbe1[tid] = be1[tid];
    else           sbe2[tid - 256] = be2[tid - 256];
    __syncthreads();

    const int wid  = tid >> 5;
    const int lane = tid & 31;
    float* myE1 = sE1 + wid * 1024;   // 8 rows x 128
    float* myX  = sX  + wid * 128;    // 8 rows x 16
    const int jj = lane * 4;

    float cs1[2][4] = {{0.f,0.f,0.f,0.f},{0.f,0.f,0.f,0.f}};
    float cs2[4] = {0.f,0.f,0.f,0.f};

    float* g_inc1 = g_scr + OFF_INC1;
    float* g_out1 = g_scr + OFF_OUT1;
    float* g_inc2 = g_scr + OFF_INC2;
    float* g_out2 = g_scr + OFF_OUT2;

    const int le = lane >> 2, lq = lane & 3;   // X fill mapping

    for (int grp = blockIdx.x * NWARP + wid; grp < GRPS; grp += gridDim.x * NWARP) {
        const long base = (long)grp * 8;
        __syncwarp();   // myX/myE1 free of previous-group readers
        *(float4*)(myX + le * 16 + lq * 4) =
            *(const float4*)(edges + (base + le) * 16 + lq * 4);
        // lanes 0..7: sender idx + its invOUT; lanes 8..15: receiver idx + its invIN
        int idxreg = 0; float sclreg = 0.f;
        if (lane < 8) {
            idxreg = snd[base + lane];
            sclreg = g_scr[OFF_INVOUT + idxreg];
        } else if (lane < 16) {
            idxreg = rcv[base + lane - 8];
            sclreg = g_scr[OFF_INVIN + idxreg];
        }
        __syncwarp();

        ull acc2[8][2];
        #pragma unroll
        for (int i = 0; i < 8; i++) { acc2[i][0] = 0ull; acc2[i][1] = 0ull; }

        #pragma unroll
        for (int h = 0; h < 2; h++) {
            ull accA[8][2];
            #pragma unroll
            for (int i = 0; i < 8; i++) { accA[i][0] = 0ull; accA[i][1] = 0ull; }
            #pragma unroll
            for (int k0 = 0; k0 < 16; k0 += 4) {
                ulonglong2 w0 = *(const ulonglong2*)(sWe1 + (k0 + 0) * 256 + h * 128 + jj);
                ulonglong2 w1 = *(const ulonglong2*)(sWe1 + (k0 + 1) * 256 + h * 128 + jj);
                ulonglong2 w2 = *(const ulonglong2*)(sWe1 + (k0 + 2) * 256 + h * 128 + jj);
                ulonglong2 w3 = *(const ulonglong2*)(sWe1 + (k0 + 3) * 256 + h * 128 + jj);
                #pragma unroll
                for (int i = 0; i < 8; i++) {
                    float4 a4 = *(const float4*)(myX + i * 16 + k0);
                    ull ax = pk2(a4.x), ay = pk2(a4.y), az = pk2(a4.z), aw = pk2(a4.w);
                    ffma2(accA[i][0], ax, w0.x); ffma2(accA[i][1], ax, w0.y);
                    ffma2(accA[i][0], ay, w1.x); ffma2(accA[i][1], ay, w1.y);
                    ffma2(accA[i][0], az, w2.x); ffma2(accA[i][1], az, w2.y);
                    ffma2(accA[i][0], aw, w3.x); ffma2(accA[i][1], aw, w3.y);
                }
            }
            {
                float4 b = *(const float4*)(sbe1 + h * 128 + jj);
                #pragma unroll
                for (int i = 0; i < 8; i++) {
                    float2 t0 = up2(accA[i][0]), t1 = up2(accA[i][1]);
                    float4 r;
                    r.x = fmaxf(t0.x + b.x, 0.f); r.y = fmaxf(t0.y + b.y, 0.f);
                    r.z = fmaxf(t1.x + b.z, 0.f); r.w = fmaxf(t1.y + b.w, 0.f);
                    *(float4*)(myE1 + i * 128 + jj) = r;
                    cs1[h][0] += r.x; cs1[h][1] += r.y; cs1[h][2] += r.z; cs1[h][3] += r.w;
                    int rI = __shfl_sync(0xffffffffu, idxreg, 8 + i);
                    int sI = __shfl_sync(0xffffffffu, idxreg, i);
                    float fI = __shfl_sync(0xffffffffu, sclreg, 8 + i);
                    float fO = __shfl_sync(0xffffffffu, sclreg, i);
                    red4(g_inc1 + (long)rI * 256 + h * 128 + jj,
                         r.x * fI, r.y * fI, r.z * fI, r.w * fI);
                    red4(g_out1 + (long)sI * 256 + h * 128 + jj,
                         r.x * fO, r.y * fO, r.z * fO, r.w * fO);
                }
            }
            __syncwarp();

            #pragma unroll 4
            for (int k0 = 0; k0 < 128; k0 += 4) {
                ulonglong2 w0 = *(const ulonglong2*)(sWe2 + (h * 128 + k0 + 0) * 128 + jj);
                ulonglong2 w1 = *(const ulonglong2*)(sWe2 + (h * 128 + k0 + 1) * 128 + jj);
                ulonglong2 w2 = *(const ulonglong2*)(sWe2 + (h * 128 + k0 + 2) * 128 + jj);
                ulonglong2 w3 = *(const ulonglong2*)(sWe2 + (h * 128 + k0 + 3) * 128 + jj);
                #pragma unroll
                for (int i = 0; i < 8; i++) {
                    float4 a4 = *(const float4*)(myE1 + i * 128 + k0);
                    ull ax = pk2(a4.x), ay = pk2(a4.y), az = pk2(a4.z), aw = pk2(a4.w);
                    ffma2(acc2[i][0], ax, w0.x); ffma2(acc2[i][1], ax, w0.y);
                    ffma2(acc2[i][0], ay, w1.x); ffma2(acc2[i][1], ay, w1.y);
                    ffma2(acc2[i][0], az, w2.x); ffma2(acc2[i][1], az, w2.y);
                    ffma2(acc2[i][0], aw, w3.x); ffma2(acc2[i][1], aw, w3.y);
                }
            }
            __syncwarp();
        }

        {
            float4 b = *(const float4*)(sbe2 + jj);
            #pragma unroll
            for (int i = 0; i < 8; i++) {
                float2 t0 = up2(acc2[i][0]), t1 = up2(acc2[i][1]);
                float4 r;
                r.x = fmaxf(t0.x + b.x, 0.f); r.y = fmaxf(t0.y + b.y, 0.f);
                r.z = fmaxf(t1.x + b.z, 0.f); r.w = fmaxf(t1.y + b.w, 0.f);
                *(float4*)(e2_out + (base + i) * 128 + jj) = r;
                cs2[0] += r.x; cs2[1] += r.y; cs2[2] += r.z; cs2[3] += r.w;
                int rI = __shfl_sync(0xffffffffu, idxreg, 8 + i);
                int sI = __shfl_sync(0xffffffffu, idxreg, i);
                float fI = __shfl_sync(0xffffffffu, sclreg, 8 + i);
                float fO = __shfl_sync(0xffffffffu, sclreg, i);
                red4(g_inc2 + (long)rI * 128 + jj,
                     r.x * fI, r.y * fI, r.z * fI, r.w * fI);
                red4(g_out2 + (long)sI * 128 + jj,
                     r.x * fO, r.y * fO, r.z * fO, r.w * fO);
            }
        }
    }
    red4(g_scr + OFF_E1SUM + jj,       cs1[0][0], cs1[0][1], cs1[0][2], cs1[0][3]);
    red4(g_scr + OFF_E1SUM + 128 + jj, cs1[1][0], cs1[1][1], cs1[1][2], cs1[1][3]);
    red4(g_scr + OFF_E2SUM + jj,       cs2[0], cs2[1], cs2[2], cs2[3]);
}

// ---------------- fused node kernel (cp.async, NO scaling needed) ----------
#define K2_TILES 782
#define NC1 34
#define NC2 32

__device__ __forceinline__ void g1_issue(int c, int base, float* sWb, float* sAb,
        const float* Wn1, const float* Win1, const float* Wout1,
        const float* nodes, const float* inc1, const float* out1,
        int tid, int an, int aq)
{
    const float* Wsrc; int kb;
    if (c < 2)       { Wsrc = Wn1;   kb = c * 16; }
    else if (c < 18) { Wsrc = Win1;  kb = (c - 2) * 16; }
    else             { Wsrc = Wout1; kb = (c - 18) * 16; }
    uint32_t wdst = s2u(sWb);
    #pragma unroll
    for (int r = 0; r < 4; r++) {
        int q = tid + r * 256;
        int k = q >> 6, j = (q & 63) * 4;
        cpa16(wdst + (uint32_t)(k * 256 + j) * 4, Wsrc + (long)(kb + k) * 256 + j);
    }
    int node = base + an;
    uint32_t adst = s2u(sAb) + (uint32_t)(an * 16 + aq) * 4;
    if (c < 2) {
        int ns = node < NN ? node : NN - 1;
        cpa16z(adst, nodes + (long)ns * 32 + c * 16 + aq, node < NN);
    } else if (c < 18) {
        cpa16(adst, inc1 + (long)node * 256 + (c - 2) * 16 + aq);
    } else {
        cpa16(adst, out1 + (long)node * 256 + (c - 18) * 16 + aq);
    }
}

__device__ __forceinline__ void g2_issue(int c, int base, float* sWb, float* sAb,
        const float* Wn2, const float* Win2, const float* Wout2,
        const float* inc2, const float* out2,
        int tid, int an, int aq)
{
    const float* Wsrc; int kb;
    if (c < 16)      { Wsrc = Wn2;   kb = c * 16; }
    else if (c < 24) { Wsrc = Win2;  kb = (c - 16) * 16; }
    else             { Wsrc = Wout2; kb = (c - 24) * 16; }
    uint32_t wdst = s2u(sWb);
    #pragma unroll
    for (int r = 0; r < 2; r++) {
        int q = tid + r * 256;
        int k = q >> 5, j = (q & 31) * 4;
        cpa16(wdst + (uint32_t)(k * 128 + j) * 4, Wsrc + (long)(kb + k) * 128 + j);
    }
    if (c >= 16) {
        int node = base + an;
        uint32_t adst = s2u(sAb) + (uint32_t)(an * 16 + aq) * 4;
        if (c < 24) cpa16(adst, inc2 + (long)node * 128 + (c - 16) * 16 + aq);
        else        cpa16(adst, out2 + (long)node * 128 + (c - 24) * 16 + aq);
    }
}

__global__ void __launch_bounds__(256, 2) k_nodes(
    const float* __restrict__ nodes,
    const float* __restrict__ Wn1, const float* __restrict__ Win1,
    const float* __restrict__ Wout1, const float* __restrict__ bn1,
    const float* __restrict__ Wn2, const float* __restrict__ Win2,
    const float* __restrict__ Wout2, const float* __restrict__ bn2,
    float* __restrict__ n2_out)
{
    extern __shared__ float sm[];
    float* sN1  = sm;                       // 16384
    float* sW0  = sN1 + 16384;              // 4096
    float* sW1  = sW0 + 4096;               // 4096
    float* sA0  = sW1 + 4096;               // 1024
    float* sA1  = sA0 + 1024;               // 1024
    float* sbn1 = sA1 + 1024;               // 256
    float* sbn2 = sbn1 + 256;               // 128
    // total = 27008 floats = 108032 B (2 CTAs/SM)

    const int tid = threadIdx.x;
    if (tid < 256) sbn1[tid] = bn1[tid];
    if (tid < 128) sbn2[tid] = bn2[tid];

    const int ig  = tid >> 5;
    const int jg  = tid & 31;
    const int n0  = ig * 8;
    const int jj  = jg * 8;
    const int jj2 = jg * 4;
    const int an  = tid >> 2;
    const int aq  = (tid & 3) * 4;

    float csn1[8] = {0.f,0.f,0.f,0.f,0.f,0.f,0.f,0.f};
    float csn2[4] = {0.f,0.f,0.f,0.f};

    const float* g_inc1 = g_scr + OFF_INC1;
    const float* g_out1 = g_scr + OFF_OUT1;
    const float* g_inc2 = g_scr + OFF_INC2;
    const float* g_out2 = g_scr + OFF_OUT2;

    for (int tile = blockIdx.x; tile < K2_TILES; tile += gridDim.x) {
        const int base = tile * 64;

        // ================= GEMM1: 34 chunks of 16 k, double-buffered =========
        ull acc1[8][4];
        #pragma unroll
        for (int i = 0; i < 8; i++)
            #pragma unroll
            for (int q = 0; q < 4; q++) acc1[i][q] = 0ull;

        g1_issue(0, base, sW0, sA0, Wn1, Win1, Wout1, nodes, g_inc1, g_out1, tid, an, aq);
        CPA_COMMIT();
        for (int c = 0; c < NC1; c++) {
            float* sWb = (c & 1) ? sW1 : sW0;
            float* sAb = (c & 1) ? sA1 : sA0;
            if (c + 1 < NC1) {
                g1_issue(c + 1, base, (c & 1) ? sW0 : sW1, (c & 1) ? sA0 : sA1,
                         Wn1, Win1, Wout1, nodes, g_inc1, g_out1, tid, an, aq);
                CPA_COMMIT();
                CPA_WAIT1();
            } else {
                CPA_WAIT0();
            }
            __syncthreads();   // chunk c visible everywhere
            #pragma unroll 2
            for (int k = 0; k < 16; k++) {
                ulonglong2 w01 = *(const ulonglong2*)(sWb + k * 256 + jj);
                ulonglong2 w23 = *(const ulonglong2*)(sWb + k * 256 + jj + 4);
                #pragma unroll
                for (int i = 0; i < 8; i++) {
                    ull a = pk2(sAb[(n0 + i) * 16 + k]);
                    ffma2(acc1[i][0], a, w01.x);
                    ffma2(acc1[i][1], a, w01.y);
                    ffma2(acc1[i][2], a, w23.x);
                    ffma2(acc1[i][3], a, w23.y);
                }
            }
            __syncthreads();   // reads done before next overwrite
        }
        // epilogue: n1 -> sN1 (+colsum)
        {
            float4 b0 = *(const float4*)(sbn1 + jj);
            float4 b1 = *(const float4*)(sbn1 + jj + 4);
            #pragma unroll
            for (int i = 0; i < 8; i++) {
                bool valid = (base + n0 + i) < NN;
                float2 t0 = up2(acc1[i][0]), t1 = up2(acc1[i][1]);
                float2 t2 = up2(acc1[i][2]), t3 = up2(acc1[i][3]);
                float4 r0, r1;
                r0.x = valid ? fmaxf(t0.x + b0.x, 0.f) : 0.f;
                r0.y = valid ? fmaxf(t0.y + b0.y, 0.f) : 0.f;
                r0.z = valid ? fmaxf(t1.x + b0.z, 0.f) : 0.f;
                r0.w = valid ? fmaxf(t1.y + b0.w, 0.f) : 0.f;
                r1.x = valid ? fmaxf(t2.x + b1.x, 0.f) : 0.f;
                r1.y = valid ? fmaxf(t2.y + b1.y, 0.f) : 0.f;
                r1.z = valid ? fmaxf(t3.x + b1.z, 0.f) : 0.f;
                r1.w = valid ? fmaxf(t3.y + b1.w, 0.f) : 0.f;
                *(float4*)(sN1 + (n0 + i) * 256 + jj)     = r0;
                *(float4*)(sN1 + (n0 + i) * 256 + jj + 4) = r1;
                csn1[0] += r0.x; csn1[1] += r0.y; csn1[2] += r0.z; csn1[3] += r0.w;
                csn1[4] += r1.x; csn1[5] += r1.y; csn1[6] += r1.z; csn1[7] += r1.w;
            }
        }

        // ================= GEMM2: 32 chunks of 16 k, double-buffered =========
        ull acc2[8][2];
        #pragma unroll
        for (int i = 0; i < 8; i++) { acc2[i][0] = 0ull; acc2[i][1] = 0ull; }

        g2_issue(0, base, sW0, sA0, Wn2, Win2, Wout2, g_inc2, g_out2, tid, an, aq);
        CPA_COMMIT();
        for (int c = 0; c < NC2; c++) {
            float* sWb = (c & 1) ? sW1 : sW0;
            float* sAb = (c & 1) ? sA1 : sA0;
            if (c + 1 < NC2) {
                g2_issue(c + 1, base, (c & 1) ? sW0 : sW1, (c & 1) ? sA0 : sA1,
                         Wn2, Win2, Wout2, g_inc2, g_out2, tid, an, aq);
                CPA_COMMIT();
                CPA_WAIT1();
            } else {
                CPA_WAIT0();
            }
            __syncthreads();   // chunk c ready; also orders sN1 epilogue writes
            if (c < 16) {
                #pragma unroll 2
                for (int k = 0; k < 16; k++) {
                    ulonglong2 w = *(const ulonglong2*)(sWb + k * 128 + jj2);
                    #pragma unroll
                    for (int i = 0; i < 8; i++) {
                        ull a = pk2(sN1[(n0 + i) * 256 + c * 16 + k]);
                        ffma2(acc2[i][0], a, w.x);
                        ffma2(acc2[i][1], a, w.y);
                    }
                }
            } else {
                #pragma unroll 2
                for (int k = 0; k < 16; k++) {
                    ulonglong2 w = *(const ulonglong2*)(sWb + k * 128 + jj2);
                    #pragma unroll
                    for (int i = 0; i < 8; i++) {
                        ull a = pk2(sAb[(n0 + i) * 16 + k]);
                        ffma2(acc2[i][0], a, w.x);
                        ffma2(acc2[i][1], a, w.y);
                    }
                }
            }
            __syncthreads();
        }
        // epilogue: n2 -> global (+colsum)
        {
            float4 b0 = *(const float4*)(sbn2 + jj2);
            #pragma unroll
            for (int i = 0; i < 8; i++) {
                int node = base + n0 + i;
                if (node < NN) {
                    float2 t0 = up2(acc2[i][0]), t1 = up2(acc2[i][1]);
                    float4 r0;
                    r0.x = fmaxf(t0.x + b0.x, 0.f);
                    r0.y = fmaxf(t0.y + b0.y, 0.f);
                    r0.z = fmaxf(t1.x + b0.z, 0.f);
                    r0.w = fmaxf(t1.y + b0.w, 0.f);
                    *(float4*)(n2_out + (long)node * 128 + jj2) = r0;
                    csn2[0] += r0.x; csn2[1] += r0.y; csn2[2] += r0.z; csn2[3] += r0.w;
                }
            }
        }
    }
    red4(g_scr + OFF_N1SUM + jj,     csn1[0], csn1[1], csn1[2], csn1[3]);
    red4(g_scr + OFF_N1SUM + jj + 4, csn1[4], csn1[5], csn1[6], csn1[7]);
    red4(g_scr + OFF_N2SUM + jj2,    csn2[0], csn2[1], csn2[2], csn2[3]);
}

// ---------------- globals kernel ----------------
__global__ void k_glob(
    const float* __restrict__ gu,
    const float* __restrict__ Wu1, const float* __restrict__ Wgn1,
    const float* __restrict__ Wge1, const float* __restrict__ bu1,
    const float* __restrict__ Wu2, const float* __restrict__ Wgn2,
    const float* __restrict__ Wge2, const float* __restrict__ bu2,
    float* __restrict__ u2_out)
{
    __shared__ float su1[256];
    __shared__ float sgu[16];
    __shared__ float sn1m[256], se1m[256];
    const int tid = threadIdx.x;
    if (tid < 16) sgu[tid] = gu[tid];
    sn1m[tid] = g_scr[OFF_N1SUM + tid] * (1.0f / NN);
    se1m[tid] = g_scr[OFF_E1SUM + tid] * (1.0f / EE);
    __syncthreads();
    {
        float s = bu1[tid];
        #pragma unroll 4
        for (int k = 0; k < 16; k++) s = fmaf(sgu[k], Wu1[k * 256 + tid], s);
        #pragma unroll 4
        for (int k = 0; k < 256; k++) {
            s = fmaf(sn1m[k], Wgn1[k * 256 + tid], s);
            s = fmaf(se1m[k], Wge1[k * 256 + tid], s);
        }
        su1[tid] = fmaxf(s, 0.f);
    }
    __syncthreads();
    if (tid < 128) {
        float s = bu2[tid];
        #pragma unroll 4
        for (int k = 0; k < 256; k++) s = fmaf(su1[k], Wu2[k * 128 + tid], s);
        #pragma unroll 4
        for (int k = 0; k < 128; k++) {
            s = fmaf(g_scr[OFF_N2SUM + k] * (1.0f / NN), Wgn2[k * 128 + tid], s);
            s = fmaf(g_scr[OFF_E2SUM + k] * (1.0f / EE), Wge2[k * 128 + tid], s);
        }
        u2_out[tid] = fmaxf(s, 0.f);
    }
}

extern "C" void kernel_launch(void* const* d_in, const int* in_sizes, int n_in,
                              void* d_out, int out_size) {
    const float* nodes = (const float*)d_in[0];
    const float* edges = (const float*)d_in[1];
    const float* gu    = (const float*)d_in[2];
    const int*   snd   = (const int*)d_in[3];
    const int*   rcv   = (const int*)d_in[4];
    const float* We1 = (const float*)d_in[5];
    const float* be1 = (const float*)d_in[6];
    const float* Wn1 = (const float*)d_in[7];
    const float* Win1 = (const float*)d_in[8];
    const float* Wout1 = (const float*)d_in[9];
    const float* bn1 = (const float*)d_in[10];
    const float* Wu1 = (const float*)d_in[11];
    const float* Wgn1 = (const float*)d_in[12];
    const float* Wge1 = (const float*)d_in[13];
    const float* bu1 = (const float*)d_in[14];
    const float* We2 = (const float*)d_in[15];
    const float* be2 = (const float*)d_in[16];
    const float* Wn2 = (const float*)d_in[17];
    const float* Win2 = (const float*)d_in[18];
    const float* Wout2 = (const float*)d_in[19];
    const float* bn2 = (const float*)d_in[20];
    const float* Wu2 = (const float*)d_in[21];
    const float* Wgn2 = (const float*)d_in[22];
    const float* Wge2 = (const float*)d_in[23];
    const float* bu2 = (const float*)d_in[24];

    float* out    = (float*)d_out;
    float* n2_out = out;
    float* e2_out = out + (long)NN * H2;                       // 6,400,000
    float* u2_out = out + (long)NN * H2 + (long)EE * H2;       // 57,600,000

    const int SMEM_K1 = (32768 + 4096 + 12288 + 1536 + 256 + 128) * 4;   // 204288
    const int SMEM_K2 = (16384 + 4096 + 4096 + 1024 + 1024 + 256 + 128) * 4; // 108032
    cudaFuncSetAttribute(k_edges, cudaFuncAttributeMaxDynamicSharedMemorySize, SMEM_K1);
    cudaFuncSetAttribute(k_nodes, cudaFuncAttributeMaxDynamicSharedMemorySize, SMEM_K2);

    k_zero<<<(ZERO_FLOATS / 4 + 255) / 256, 256>>>();
    k_deg<<<(EE + 255) / 256, 256>>>(snd, rcv);
    k_inv<<<(NN + 255) / 256, 256>>>();
    k_edges<<<148, NT, SMEM_K1>>>(edges, snd, rcv, We1, be1, We2, be2, e2_out);
    k_nodes<<<296, 256, SMEM_K2>>>(nodes, Wn1, Win1, Wout1, bn1,
                                   Wn2, Win2, Wout2, bn2, n2_out);
    k_glob<<<1, 256>>>(gu, Wu1, Wgn1, Wge1, bu1, Wu2, Wgn2, Wge2, bu2, u2_out);
}

// round 10
// speedup vs baseline: 1.0292x; 1.0292x over previous
#include <cuda_runtime.h>
#include <cstdint>

#define NN 50000
#define EE 400000
#define H1 256
#define H2 128

// ---- scratch layout (floats) ----
#define OFF_INC1   0                       // N*256
#define OFF_OUT1   12800000                // N*256
#define OFF_INC2   25600000                // N*128
#define OFF_OUT2   32000000                // N*128
#define OFF_E1SUM  38400000                // 256
#define OFF_E2SUM  38400256                // 128
#define OFF_N1SUM  38400384                // 256
#define OFF_N2SUM  38400640                // 128
#define OFF_INVIN  38400768                // N
#define OFF_INVOUT 38450768                // N
#define SCR_TOTAL  38500864
#define ZERO_FLOATS 38400768               // [0, OFF_INVIN) must be zeroed

__device__ float g_scr[SCR_TOTAL];
__device__ int   g_cnt[2 * NN];

typedef unsigned long long ull;

__device__ __forceinline__ void red4(float* p, float a, float b, float c, float d) {
    asm volatile("red.global.add.v4.f32 [%0], {%1,%2,%3,%4};"
                 :: "l"(p), "f"(a), "f"(b), "f"(c), "f"(d) : "memory");
}
__device__ __forceinline__ ull pk2(float x) {
    ull r; asm("mov.b64 %0, {%1, %1};" : "=l"(r) : "f"(x)); return r;
}
__device__ __forceinline__ void ffma2(ull& acc, ull a, ull b) {
    asm("fma.rn.f32x2 %0, %1, %2, %0;" : "+l"(acc) : "l"(a), "l"(b));
}
__device__ __forceinline__ float2 up2(ull v) {
    float2 f; asm("mov.b64 {%0, %1}, %2;" : "=f"(f.x), "=f"(f.y) : "l"(v)); return f;
}
__device__ __forceinline__ uint32_t s2u(const void* p) {
    return (uint32_t)__cvta_generic_to_shared(p);
}
__device__ __forceinline__ void cpa16(uint32_t dst, const void* src) {
    asm volatile("cp.async.cg.shared.global [%0], [%1], 16;" :: "r"(dst), "l"(src));
}
__device__ __forceinline__ void cpa16z(uint32_t dst, const void* src, int ok) {
    asm volatile("cp.async.cg.shared.global [%0], [%1], 16, %2;"
                 :: "r"(dst), "l"(src), "r"(ok ? 16 : 0));
}
#define CPA_COMMIT() asm volatile("cp.async.commit_group;" ::: "memory")
#define CPA_WAIT1()  asm volatile("cp.async.wait_group 1;" ::: "memory")
#define CPA_WAIT0()  asm volatile("cp.async.wait_group 0;" ::: "memory")

// ---------------- zero scratch ----------------
__global__ void k_zero() {
    long i = (long)blockIdx.x * 256 + threadIdx.x;
    if (i < ZERO_FLOATS / 4) {
        float4 z = {0.f, 0.f, 0.f, 0.f};
        *(float4*)(g_scr + i * 4) = z;
    }
    if (i < (2 * NN) / 4) {
        int4 z = {0, 0, 0, 0};
        *(int4*)(g_cnt + i * 4) = z;
    }
}

// ---------------- degrees ----------------
__global__ void k_deg(const int* __restrict__ snd, const int* __restrict__ rcv) {
    int i = blockIdx.x * 256 + threadIdx.x;
    if (i < EE) {
        atomicAdd(&g_cnt[rcv[i]], 1);
        atomicAdd(&g_cnt[NN + snd[i]], 1);
    }
}

__global__ void k_inv() {
    int i = blockIdx.x * 256 + threadIdx.x;
    if (i < NN) {
        int ci = g_cnt[i];      g_scr[OFF_INVIN  + i] = 1.0f / (float)(ci > 1 ? ci : 1);
        int co = g_cnt[NN + i]; g_scr[OFF_INVOUT + i] = 1.0f / (float)(co > 1 ? co : 1);
    }
}

// ---------------- fused edge kernel (12 warps, 8 rows/warp) ----------------
// Scatter contributions are pre-scaled by the target node's inverse degree,
// so inc/out buffers directly hold segment MEANS (k_nodes does no scaling).
#define GRPS 50000   /* EE / 8 */
#define NWARP 12
#define NT 384
__global__ void __launch_bounds__(NT, 1) k_edges(
    const float* __restrict__ edges, const int* __restrict__ snd, const int* __restrict__ rcv,
    const float* __restrict__ We1, const float* __restrict__ be1,
    const float* __restrict__ We2, const float* __restrict__ be2,
    float* __restrict__ e2_out)
{
    extern __shared__ float sm[];
    float* sWe2 = sm;                 // 256*128 = 32768
    float* sWe1 = sWe2 + 32768;       // 16*256  = 4096
    float* sE1  = sWe1 + 4096;        // 12 warps * 8*128 = 12288
    float* sX   = sE1 + 12288;        // 12 warps * 8*16  = 1536
    float* sbe1 = sX + 1536;          // 256
    float* sbe2 = sbe1 + 256;         // 128

    const int tid = threadIdx.x;
    for (int i = tid; i < 32768; i += NT) sWe2[i] = We2[i];
    for (int i = tid; i < 4096;  i += NT) sWe1[i] = We1[i];
    if (tid < 256) sbe1[tid] = be1[tid];
    else           sbe2[tid - 256] = be2[tid - 256];
    __syncthreads();

    const int wid  = tid >> 5;
    const int lane = tid & 31;
    float* myE1 = sE1 + wid * 1024;   // 8 rows x 128
    float* myX  = sX  + wid * 128;    // 8 rows x 16
    const int jj = lane * 4;

    float cs1[2][4] = {{0.f,0.f,0.f,0.f},{0.f,0.f,0.f,0.f}};
    float cs2[4] = {0.f,0.f,0.f,0.f};

    float* g_inc1 = g_scr + OFF_INC1;
    float* g_out1 = g_scr + OFF_OUT1;
    float* g_inc2 = g_scr + OFF_INC2;
    float* g_out2 = g_scr + OFF_OUT2;

    const int le = lane >> 2, lq = lane & 3;   // X fill mapping

    for (int grp = blockIdx.x * NWARP + wid; grp < GRPS; grp += gridDim.x * NWARP) {
        const long base = (long)grp * 8;
        __syncwarp();   // myX/myE1 free of previous-group readers
        *(float4*)(myX + le * 16 + lq * 4) =
            *(const float4*)(edges + (base + le) * 16 + lq * 4);
        // lanes 0..7: sender idx + its invOUT; lanes 8..15: receiver idx + its invIN
        int idxreg = 0; float sclreg = 0.f;
        if (lane < 8) {
            idxreg = snd[base + lane];
            sclreg = g_scr[OFF_INVOUT + idxreg];
        } else if (lane < 16) {
            idxreg = rcv[base + lane - 8];
            sclreg = g_scr[OFF_INVIN + idxreg];
        }
        __syncwarp();

        ull acc2[8][2];
        #pragma unroll
        for (int i = 0; i < 8; i++) { acc2[i][0] = 0ull; acc2[i][1] = 0ull; }

        #pragma unroll
        for (int h = 0; h < 2; h++) {
            ull accA[8][2];
            #pragma unroll
            for (int i = 0; i < 8; i++) { accA[i][0] = 0ull; accA[i][1] = 0ull; }
            #pragma unroll
            for (int k0 = 0; k0 < 16; k0 += 4) {
                ulonglong2 w0 = *(const ulonglong2*)(sWe1 + (k0 + 0) * 256 + h * 128 + jj);
                ulonglong2 w1 = *(const ulonglong2*)(sWe1 + (k0 + 1) * 256 + h * 128 + jj);
                ulonglong2 w2 = *(const ulonglong2*)(sWe1 + (k0 + 2) * 256 + h * 128 + jj);
                ulonglong2 w3 = *(const ulonglong2*)(sWe1 + (k0 + 3) * 256 + h * 128 + jj);
                #pragma unroll
                for (int i = 0; i < 8; i++) {
                    float4 a4 = *(const float4*)(myX + i * 16 + k0);
                    ull ax = pk2(a4.x), ay = pk2(a4.y), az = pk2(a4.z), aw = pk2(a4.w);
                    ffma2(accA[i][0], ax, w0.x); ffma2(accA[i][1], ax, w0.y);
                    ffma2(accA[i][0], ay, w1.x); ffma2(accA[i][1], ay, w1.y);
                    ffma2(accA[i][0], az, w2.x); ffma2(accA[i][1], az, w2.y);
                    ffma2(accA[i][0], aw, w3.x); ffma2(accA[i][1], aw, w3.y);
                }
            }
            {
                float4 b = *(const float4*)(sbe1 + h * 128 + jj);
                #pragma unroll
                for (int i = 0; i < 8; i++) {
                    float2 t0 = up2(accA[i][0]), t1 = up2(accA[i][1]);
                    float4 r;
                    r.x = fmaxf(t0.x + b.x, 0.f); r.y = fmaxf(t0.y + b.y, 0.f);
                    r.z = fmaxf(t1.x + b.z, 0.f); r.w = fmaxf(t1.y + b.w, 0.f);
                    *(float4*)(myE1 + i * 128 + jj) = r;
                    cs1[h][0] += r.x; cs1[h][1] += r.y; cs1[h][2] += r.z; cs1[h][3] += r.w;
                    int rI = __shfl_sync(0xffffffffu, idxreg, 8 + i);
                    int sI = __shfl_sync(0xffffffffu, idxreg, i);
                    float fI = __shfl_sync(0xffffffffu, sclreg, 8 + i);
                    float fO = __shfl_sync(0xffffffffu, sclreg, i);
                    red4(g_inc1 + (long)rI * 256 + h * 128 + jj,
                         r.x * fI, r.y * fI, r.z * fI, r.w * fI);
                    red4(g_out1 + (long)sI * 256 + h * 128 + jj,
                         r.x * fO, r.y * fO, r.z * fO, r.w * fO);
                }
            }
            __syncwarp();

            #pragma unroll 4
            for (int k0 = 0; k0 < 128; k0 += 4) {
                ulonglong2 w0 = *(const ulonglong2*)(sWe2 + (h * 128 + k0 + 0) * 128 + jj);
                ulonglong2 w1 = *(const ulonglong2*)(sWe2 + (h * 128 + k0 + 1) * 128 + jj);
                ulonglong2 w2 = *(const ulonglong2*)(sWe2 + (h * 128 + k0 + 2) * 128 + jj);
                ulonglong2 w3 = *(const ulonglong2*)(sWe2 + (h * 128 + k0 + 3) * 128 + jj);
                #pragma unroll
                for (int i = 0; i < 8; i++) {
                    float4 a4 = *(const float4*)(myE1 + i * 128 + k0);
                    ull ax = pk2(a4.x), ay = pk2(a4.y), az = pk2(a4.z), aw = pk2(a4.w);
                    ffma2(acc2[i][0], ax, w0.x); ffma2(acc2[i][1], ax, w0.y);
                    ffma2(acc2[i][0], ay, w1.x); ffma2(acc2[i][1], ay, w1.y);
                    ffma2(acc2[i][0], az, w2.x); ffma2(acc2[i][1], az, w2.y);
                    ffma2(acc2[i][0], aw, w3.x); ffma2(acc2[i][1], aw, w3.y);
                }
            }
            __syncwarp();
        }

        {
            float4 b = *(const float4*)(sbe2 + jj);
            #pragma unroll
            for (int i = 0; i < 8; i++) {
                float2 t0 = up2(acc2[i][0]), t1 = up2(acc2[i][1]);
                float4 r;
                r.x = fmaxf(t0.x + b.x, 0.f); r.y = fmaxf(t0.y + b.y, 0.f);
                r.z = fmaxf(t1.x + b.z, 0.f); r.w = fmaxf(t1.y + b.w, 0.f);
                *(float4*)(e2_out + (base + i) * 128 + jj) = r;
                cs2[0] += r.x; cs2[1] += r.y; cs2[2] += r.z; cs2[3] += r.w;
                int rI = __shfl_sync(0xffffffffu, idxreg, 8 + i);
                int sI = __shfl_sync(0xffffffffu, idxreg, i);
                float fI = __shfl_sync(0xffffffffu, sclreg, 8 + i);
                float fO = __shfl_sync(0xffffffffu, sclreg, i);
                red4(g_inc2 + (long)rI * 128 + jj,
                     r.x * fI, r.y * fI, r.z * fI, r.w * fI);
                red4(g_out2 + (long)sI * 128 + jj,
                     r.x * fO, r.y * fO, r.z * fO, r.w * fO);
            }
        }
    }
    red4(g_scr + OFF_E1SUM + jj,       cs1[0][0], cs1[0][1], cs1[0][2], cs1[0][3]);
    red4(g_scr + OFF_E1SUM + 128 + jj, cs1[1][0], cs1[1][1], cs1[1][2], cs1[1][3]);
    red4(g_scr + OFF_E2SUM + jj,       cs2[0], cs2[1], cs2[2], cs2[3]);
}

// ---------------- fused node kernel (split-column GEMM1: conflict-free LDS) --
#define K2_TILES 782
#define NC1 34
#define NC2 32

__device__ __forceinline__ void g1_issue(int c, int base, float* sWb, float* sAb,
        const float* Wn1, const float* Win1, const float* Wout1,
        const float* nodes, const float* inc1, const float* out1,
        int tid, int an, int aq)
{
    const float* Wsrc; int kb;
    if (c < 2)       { Wsrc = Wn1;   kb = c * 16; }
    else if (c < 18) { Wsrc = Win1;  kb = (c - 2) * 16; }
    else             { Wsrc = Wout1; kb = (c - 18) * 16; }
    uint32_t wdst = s2u(sWb);
    #pragma unroll
    for (int r = 0; r < 4; r++) {
        int q = tid + r * 256;
        int k = q >> 6, j = (q & 63) * 4;
        cpa16(wdst + (uint32_t)(k * 256 + j) * 4, Wsrc + (long)(kb + k) * 256 + j);
    }
    int node = base + an;
    uint32_t adst = s2u(sAb) + (uint32_t)(an * 16 + aq) * 4;
    if (c < 2) {
        int ns = node < NN ? node : NN - 1;
        cpa16z(adst, nodes + (long)ns * 32 + c * 16 + aq, node < NN);
    } else if (c < 18) {
        cpa16(adst, inc1 + (long)node * 256 + (c - 2) * 16 + aq);
    } else {
        cpa16(adst, out1 + (long)node * 256 + (c - 18) * 16 + aq);
    }
}

__device__ __forceinline__ void g2_issue(int c, int base, float* sWb, float* sAb,
        const float* Wn2, const float* Win2, const float* Wout2,
        const float* inc2, const float* out2,
        int tid, int an, int aq)
{
    const float* Wsrc; int kb;
    if (c < 16)      { Wsrc = Wn2;   kb = c * 16; }
    else if (c < 24) { Wsrc = Win2;  kb = (c - 16) * 16; }
    else             { Wsrc = Wout2; kb = (c - 24) * 16; }
    uint32_t wdst = s2u(sWb);
    #pragma unroll
    for (int r = 0; r < 2; r++) {
        int q = tid + r * 256;
        int k = q >> 5, j = (q & 31) * 4;
        cpa16(wdst + (uint32_t)(k * 128 + j) * 4, Wsrc + (long)(kb + k) * 128 + j);
    }
    if (c >= 16) {
        int node = base + an;
        uint32_t adst = s2u(sAb) + (uint32_t)(an * 16 + aq) * 4;
        if (c < 24) cpa16(adst, inc2 + (long)node * 128 + (c - 16) * 16 + aq);
        else        cpa16(adst, out2 + (long)node * 128 + (c - 24) * 16 + aq);
    }
}

__global__ void __launch_bounds__(256, 2) k_nodes(
    const float* __restrict__ nodes,
    const float* __restrict__ Wn1, const float* __restrict__ Win1,
    const float* __restrict__ Wout1, const float* __restrict__ bn1,
    const float* __restrict__ Wn2, const float* __restrict__ Win2,
    const float* __restrict__ Wout2, const float* __restrict__ bn2,
    float* __restrict__ n2_out)
{
    extern __shared__ float sm[];
    float* sN1  = sm;                       // 16384
    float* sW0  = sN1 + 16384;              // 4096
    float* sW1  = sW0 + 4096;               // 4096
    float* sA0  = sW1 + 4096;               // 1024
    float* sA1  = sA0 + 1024;               // 1024
    float* sbn1 = sA1 + 1024;               // 256
    float* sbn2 = sbn1 + 256;               // 128
    // total = 27008 floats = 108032 B (2 CTAs/SM)

    const int tid = threadIdx.x;
    if (tid < 256) sbn1[tid] = bn1[tid];
    if (tid < 128) sbn2[tid] = bn2[tid];

    const int ig  = tid >> 5;
    const int jg  = tid & 31;
    const int n0  = ig * 8;
    const int jja = jg * 4;            // GEMM1 half A: cols [jja, jja+4)
    const int jjb = 128 + jg * 4;      // GEMM1 half B: cols [jjb, jjb+4)
    const int jj2 = jg * 4;            // GEMM2: cols [jj2, jj2+4)
    const int an  = tid >> 2;
    const int aq  = (tid & 3) * 4;

    float csn1[8] = {0.f,0.f,0.f,0.f,0.f,0.f,0.f,0.f};
    float csn2[4] = {0.f,0.f,0.f,0.f};

    const float* g_inc1 = g_scr + OFF_INC1;
    const float* g_out1 = g_scr + OFF_OUT1;
    const float* g_inc2 = g_scr + OFF_INC2;
    const float* g_out2 = g_scr + OFF_OUT2;

    for (int tile = blockIdx.x; tile < K2_TILES; tile += gridDim.x) {
        const int base = tile * 64;

        // ================= GEMM1: 34 chunks of 16 k, double-buffered =========
        ull acc1[8][4];
        #pragma unroll
        for (int i = 0; i < 8; i++)
            #pragma unroll
            for (int q = 0; q < 4; q++) acc1[i][q] = 0ull;

        g1_issue(0, base, sW0, sA0, Wn1, Win1, Wout1, nodes, g_inc1, g_out1, tid, an, aq);
        CPA_COMMIT();
        for (int c = 0; c < NC1; c++) {
            float* sWb = (c & 1) ? sW1 : sW0;
            float* sAb = (c & 1) ? sA1 : sA0;
            if (c + 1 < NC1) {
                g1_issue(c + 1, base, (c & 1) ? sW0 : sW1, (c & 1) ? sA0 : sA1,
                         Wn1, Win1, Wout1, nodes, g_inc1, g_out1, tid, an, aq);
                CPA_COMMIT();
                CPA_WAIT1();
            } else {
                CPA_WAIT0();
            }
            __syncthreads();   // chunk c visible everywhere
            #pragma unroll 2
            for (int k = 0; k < 16; k++) {
                ulonglong2 wA = *(const ulonglong2*)(sWb + k * 256 + jja);
                ulonglong2 wB = *(const ulonglong2*)(sWb + k * 256 + jjb);
                #pragma unroll
                for (int i = 0; i < 8; i++) {
                    ull a = pk2(sAb[(n0 + i) * 16 + k]);
                    ffma2(acc1[i][0], a, wA.x);
                    ffma2(acc1[i][1], a, wA.y);
                    ffma2(acc1[i][2], a, wB.x);
                    ffma2(acc1[i][3], a, wB.y);
                }
            }
            __syncthreads();   // reads done before next overwrite
        }
        // epilogue: n1 -> sN1 (+colsum); halves A and B
        {
            float4 b0 = *(const float4*)(sbn1 + jja);
            float4 b1 = *(const float4*)(sbn1 + jjb);
            #pragma unroll
            for (int i = 0; i < 8; i++) {
                bool valid = (base + n0 + i) < NN;
                float2 t0 = up2(acc1[i][0]), t1 = up2(acc1[i][1]);
                float2 t2 = up2(acc1[i][2]), t3 = up2(acc1[i][3]);
                float4 r0, r1;
                r0.x = valid ? fmaxf(t0.x + b0.x, 0.f) : 0.f;
                r0.y = valid ? fmaxf(t0.y + b0.y, 0.f) : 0.f;
                r0.z = valid ? fmaxf(t1.x + b0.z, 0.f) : 0.f;
                r0.w = valid ? fmaxf(t1.y + b0.w, 0.f) : 0.f;
                r1.x = valid ? fmaxf(t2.x + b1.x, 0.f) : 0.f;
                r1.y = valid ? fmaxf(t2.y + b1.y, 0.f) : 0.f;
                r1.z = valid ? fmaxf(t3.x + b1.z, 0.f) : 0.f;
                r1.w = valid ? fmaxf(t3.y + b1.w, 0.f) : 0.f;
                *(float4*)(sN1 + (n0 + i) * 256 + jja) = r0;
                *(float4*)(sN1 + (n0 + i) * 256 + jjb) = r1;
                csn1[0] += r0.x; csn1[1] += r0.y; csn1[2] += r0.z; csn1[3] += r0.w;
                csn1[4] += r1.x; csn1[5] += r1.y; csn1[6] += r1.z; csn1[7] += r1.w;
            }
        }

        // ================= GEMM2: 32 chunks of 16 k, double-buffered =========
        ull acc2[8][2];
        #pragma unroll
        for (int i = 0; i < 8; i++) { acc2[i][0] = 0ull; acc2[i][1] = 0ull; }

        g2_issue(0, base, sW0, sA0, Wn2, Win2, Wout2, g_inc2, g_out2, tid, an, aq);
        CPA_COMMIT();
        for (int c = 0; c < NC2; c++) {
            float* sWb = (c & 1) ? sW1 : sW0;
            float* sAb = (c & 1) ? sA1 : sA0;
            if (c + 1 < NC2) {
                g2_issue(c + 1, base, (c & 1) ? sW0 : sW1, (c & 1) ? sA0 : sA1,
                         Wn2, Win2, Wout2, g_inc2, g_out2, tid, an, aq);
                CPA_COMMIT();
                CPA_WAIT1();
            } else {
                CPA_WAIT0();
            }
            __syncthreads();   // chunk c ready; also orders sN1 epilogue writes
            if (c < 16) {
                #pragma unroll 2
                for (int k = 0; k < 16; k++) {
                    ulonglong2 w = *(const ulonglong2*)(sWb + k * 128 + jj2);
                    #pragma unroll
                    for (int i = 0; i < 8; i++) {
                        ull a = pk2(sN1[(n0 + i) * 256 + c * 16 + k]);
                        ffma2(acc2[i][0], a, w.x);
                        ffma2(acc2[i][1], a, w.y);
                    }
                }
            } else {
                #pragma unroll 2
                for (int k = 0; k < 16; k++) {
                    ulonglong2 w = *(const ulonglong2*)(sWb + k * 128 + jj2);
                    #pragma unroll
                    for (int i = 0; i < 8; i++) {
                        ull a = pk2(sAb[(n0 + i) * 16 + k]);
                        ffma2(acc2[i][0], a, w.x);
                        ffma2(acc2[i][1], a, w.y);
                    }
                }
            }
            __syncthreads();
        }
        // epilogue: n2 -> global (+colsum)
        {
            float4 b0 = *(const float4*)(sbn2 + jj2);
            #pragma unroll
            for (int i = 0; i < 8; i++) {
                int node = base + n0 + i;
                if (node < NN) {
                    float2 t0 = up2(acc2[i][0]), t1 = up2(acc2[i][1]);
                    float4 r0;
                    r0.x = fmaxf(t0.x + b0.x, 0.f);
                    r0.y = fmaxf(t0.y + b0.y, 0.f);
                    r0.z = fmaxf(t1.x + b0.z, 0.f);
                    r0.w = fmaxf(t1.y + b0.w, 0.f);
                    *(float4*)(n2_out + (long)node * 128 + jj2) = r0;
                    csn2[0] += r0.x; csn2[1] += r0.y; csn2[2] += r0.z; csn2[3] += r0.w;
                }
            }
        }
    }
    red4(g_scr + OFF_N1SUM + jja, csn1[0], csn1[1], csn1[2], csn1[3]);
    red4(g_scr + OFF_N1SUM + jjb, csn1[4], csn1[5], csn1[6], csn1[7]);
    red4(g_scr + OFF_N2SUM + jj2, csn2[0], csn2[1], csn2[2], csn2[3]);
}

// ---------------- globals kernel ----------------
__global__ void k_glob(
    const float* __restrict__ gu,
    const float* __restrict__ Wu1, const float* __restrict__ Wgn1,
    const float* __restrict__ Wge1, const float* __restrict__ bu1,
    const float* __restrict__ Wu2, const float* __restrict__ Wgn2,
    const float* __restrict__ Wge2, const float* __restrict__ bu2,
    float* __restrict__ u2_out)
{
    __shared__ float su1[256];
    __shared__ float sgu[16];
    __shared__ float sn1m[256], se1m[256];
    const int tid = threadIdx.x;
    if (tid < 16) sgu[tid] = gu[tid];
    sn1m[tid] = g_scr[OFF_N1SUM + tid] * (1.0f / NN);
    se1m[tid] = g_scr[OFF_E1SUM + tid] * (1.0f / EE);
    __syncthreads();
    {
        float s = bu1[tid];
        #pragma unroll 4
        for (int k = 0; k < 16; k++) s = fmaf(sgu[k], Wu1[k * 256 + tid], s);
        #pragma unroll 4
        for (int k = 0; k < 256; k++) {
            s = fmaf(sn1m[k], Wgn1[k * 256 + tid], s);
            s = fmaf(se1m[k], Wge1[k * 256 + tid], s);
        }
        su1[tid] = fmaxf(s, 0.f);
    }
    __syncthreads();
    if (tid < 128) {
        float s = bu2[tid];
        #pragma unroll 4
        for (int k = 0; k < 256; k++) s = fmaf(su1[k], Wu2[k * 128 + tid], s);
        #pragma unroll 4
        for (int k = 0; k < 128; k++) {
            s = fmaf(g_scr[OFF_N2SUM + k] * (1.0f / NN), Wgn2[k * 128 + tid], s);
            s = fmaf(g_scr[OFF_E2SUM + k] * (1.0f / EE), Wge2[k * 128 + tid], s);
        }
        u2_out[tid] = fmaxf(s, 0.f);
    }
}

extern "C" void kernel_launch(void* const* d_in, const int* in_sizes, int n_in,
                              void* d_out, int out_size) {
    const float* nodes = (const float*)d_in[0];
    const float* edges = (const float*)d_in[1];
    const float* gu    = (const float*)d_in[2];
    const int*   snd   = (const int*)d_in[3];
    const int*   rcv   = (const int*)d_in[4];
    const float* We1 = (const float*)d_in[5];
    const float* be1 = (const float*)d_in[6];
    const float* Wn1 = (const float*)d_in[7];
    const float* Win1 = (const float*)d_in[8];
    const float* Wout1 = (const float*)d_in[9];
    const float* bn1 = (const float*)d_in[10];
    const float* Wu1 = (const float*)d_in[11];
    const float* Wgn1 = (const float*)d_in[12];
    const float* Wge1 = (const float*)d_in[13];
    const float* bu1 = (const float*)d_in[14];
    const float* We2 = (const float*)d_in[15];
    const float* be2 = (const float*)d_in[16];
    const float* Wn2 = (const float*)d_in[17];
    const float* Win2 = (const float*)d_in[18];
    const float* Wout2 = (const float*)d_in[19];
    const float* bn2 = (const float*)d_in[20];
    const float* Wu2 = (const float*)d_in[21];
    const float* Wgn2 = (const float*)d_in[22];
    const float* Wge2 = (const float*)d_in[23];
    const float* bu2 = (const float*)d_in[24];

    float* out    = (float*)d_out;
    float* n2_out = out;
    float* e2_out = out + (long)NN * H2;                       // 6,400,000
    float* u2_out = out + (long)NN * H2 + (long)EE * H2;       // 57,600,000

    const int SMEM_K1 = (32768 + 4096 + 12288 + 1536 + 256 + 128) * 4;   // 204288
    const int SMEM_K2 = (16384 + 4096 + 4096 + 1024 + 1024 + 256 + 128) * 4; // 108032
    cudaFuncSetAttribute(k_edges, cudaFuncAttributeMaxDynamicSharedMemorySize, SMEM_K1);
    cudaFuncSetAttribute(k_nodes, cudaFuncAttributeMaxDynamicSharedMemorySize, SMEM_K2);

    k_zero<<<(ZERO_FLOATS / 4 + 255) / 256, 256>>>();
    k_deg<<<(EE + 255) / 256, 256>>>(snd, rcv);
    k_inv<<<(NN + 255) / 256, 256>>>();
    k_edges<<<148, NT, SMEM_K1>>>(edges, snd, rcv, We1, be1, We2, be2, e2_out);
    k_nodes<<<296, 256, SMEM_K2>>>(nodes, Wn1, Win1, Wout1, bn1,
                                   Wn2, Win2, Wout2, bn2, n2_out);
    k_glob<<<1, 256>>>(gu, Wu1, Wgn1, Wge1, bu1, Wu2, Wgn2, Wge2, bu2, u2_out);
}

// round 11
// speedup vs baseline: 1.0597x; 1.0296x over previous
#include <cuda_runtime.h>
#include <cstdint>

#define NN 50000
#define EE 400000
#define H1 256
#define H2 128

// ---- scratch layout (floats) ----
#define OFF_INC1   0                       // N*256
#define OFF_OUT1   12800000                // N*256
#define OFF_INC2   25600000                // N*128
#define OFF_OUT2   32000000                // N*128
#define OFF_E1SUM  38400000                // 256
#define OFF_E2SUM  38400256                // 128
#define OFF_N1SUM  38400384                // 256
#define OFF_N2SUM  38400640                // 128
#define OFF_INVIN  38400768                // N
#define OFF_INVOUT 38450768                // N
#define SCR_TOTAL  38500864
#define ZERO_FLOATS 38400768               // [0, OFF_INVIN) must be zeroed

__device__ float g_scr[SCR_TOTAL];
__device__ int   g_cnt[2 * NN];
__device__ int   g_tick[2];                // [0]=edge groups, [1]=node tiles

typedef unsigned long long ull;

__device__ __forceinline__ void red4(float* p, float a, float b, float c, float d) {
    asm volatile("red.global.add.v4.f32 [%0], {%1,%2,%3,%4};"
                 :: "l"(p), "f"(a), "f"(b), "f"(c), "f"(d) : "memory");
}
__device__ __forceinline__ ull pk2(float x) {
    ull r; asm("mov.b64 %0, {%1, %1};" : "=l"(r) : "f"(x)); return r;
}
__device__ __forceinline__ void ffma2(ull& acc, ull a, ull b) {
    asm("fma.rn.f32x2 %0, %1, %2, %0;" : "+l"(acc) : "l"(a), "l"(b));
}
__device__ __forceinline__ float2 up2(ull v) {
    float2 f; asm("mov.b64 {%0, %1}, %2;" : "=f"(f.x), "=f"(f.y) : "l"(v)); return f;
}
__device__ __forceinline__ uint32_t s2u(const void* p) {
    return (uint32_t)__cvta_generic_to_shared(p);
}
__device__ __forceinline__ void cpa16(uint32_t dst, const void* src) {
    asm volatile("cp.async.cg.shared.global [%0], [%1], 16;" :: "r"(dst), "l"(src));
}
__device__ __forceinline__ void cpa16z(uint32_t dst, const void* src, int ok) {
    asm volatile("cp.async.cg.shared.global [%0], [%1], 16, %2;"
                 :: "r"(dst), "l"(src), "r"(ok ? 16 : 0));
}
#define CPA_COMMIT() asm volatile("cp.async.commit_group;" ::: "memory")
#define CPA_WAIT1()  asm volatile("cp.async.wait_group 1;" ::: "memory")
#define CPA_WAIT0()  asm volatile("cp.async.wait_group 0;" ::: "memory")

// ---------------- zero scratch + tickets ----------------
__global__ void k_zero() {
    long i = (long)blockIdx.x * 256 + threadIdx.x;
    if (i < ZERO_FLOATS / 4) {
        float4 z = {0.f, 0.f, 0.f, 0.f};
        *(float4*)(g_scr + i * 4) = z;
    }
    if (i < (2 * NN) / 4) {
        int4 z = {0, 0, 0, 0};
        *(int4*)(g_cnt + i * 4) = z;
    }
    if (i == 0) { g_tick[0] = 0; g_tick[1] = 0; }
}

// ---------------- degrees ----------------
__global__ void k_deg(const int* __restrict__ snd, const int* __restrict__ rcv) {
    int i = blockIdx.x * 256 + threadIdx.x;
    if (i < EE) {
        atomicAdd(&g_cnt[rcv[i]], 1);
        atomicAdd(&g_cnt[NN + snd[i]], 1);
    }
}

__global__ void k_inv() {
    int i = blockIdx.x * 256 + threadIdx.x;
    if (i < NN) {
        int ci = g_cnt[i];      g_scr[OFF_INVIN  + i] = 1.0f / (float)(ci > 1 ? ci : 1);
        int co = g_cnt[NN + i]; g_scr[OFF_INVOUT + i] = 1.0f / (float)(co > 1 ? co : 1);
    }
}

// ---------------- fused edge kernel (12 warps, 8 rows/warp, ticketed) --------
// Scatter contributions pre-scaled by target node's inverse degree so
// inc/out buffers directly hold segment MEANS.
#define GRPS 50000   /* EE / 8 */
#define NWARP 12
#define NT 384
__global__ void __launch_bounds__(NT, 1) k_edges(
    const float* __restrict__ edges, const int* __restrict__ snd, const int* __restrict__ rcv,
    const float* __restrict__ We1, const float* __restrict__ be1,
    const float* __restrict__ We2, const float* __restrict__ be2,
    float* __restrict__ e2_out)
{
    extern __shared__ float sm[];
    float* sWe2 = sm;                 // 256*128 = 32768
    float* sWe1 = sWe2 + 32768;       // 16*256  = 4096
    float* sE1  = sWe1 + 4096;        // 12 warps * 8*128 = 12288
    float* sX   = sE1 + 12288;        // 12 warps * 8*16  = 1536
    float* sbe1 = sX + 1536;          // 256
    float* sbe2 = sbe1 + 256;         // 128

    const int tid = threadIdx.x;
    for (int i = tid; i < 32768; i += NT) sWe2[i] = We2[i];
    for (int i = tid; i < 4096;  i += NT) sWe1[i] = We1[i];
    if (tid < 256) sbe1[tid] = be1[tid];
    else           sbe2[tid - 256] = be2[tid - 256];
    __syncthreads();

    const int wid  = tid >> 5;
    const int lane = tid & 31;
    float* myE1 = sE1 + wid * 1024;   // 8 rows x 128
    float* myX  = sX  + wid * 128;    // 8 rows x 16
    const int jj = lane * 4;

    float cs1[2][4] = {{0.f,0.f,0.f,0.f},{0.f,0.f,0.f,0.f}};
    float cs2[4] = {0.f,0.f,0.f,0.f};

    float* g_inc1 = g_scr + OFF_INC1;
    float* g_out1 = g_scr + OFF_OUT1;
    float* g_inc2 = g_scr + OFF_INC2;
    float* g_out2 = g_scr + OFF_OUT2;

    const int le = lane >> 2, lq = lane & 3;   // X fill mapping

    // warp-level dynamic ticket
    int grp;
    if (lane == 0) grp = atomicAdd(&g_tick[0], 1);
    grp = __shfl_sync(0xffffffffu, grp, 0);

    while (grp < GRPS) {
        const long base = (long)grp * 8;
        __syncwarp();   // myX/myE1 free of previous-group readers
        *(float4*)(myX + le * 16 + lq * 4) =
            *(const float4*)(edges + (base + le) * 16 + lq * 4);
        // lanes 0..7: sender idx + invOUT; lanes 8..15: receiver idx + invIN
        int idxreg = 0; float sclreg = 0.f;
        if (lane < 8) {
            idxreg = snd[base + lane];
            sclreg = g_scr[OFF_INVOUT + idxreg];
        } else if (lane < 16) {
            idxreg = rcv[base + lane - 8];
            sclreg = g_scr[OFF_INVIN + idxreg];
        }
        __syncwarp();

        ull acc2[8][2];
        #pragma unroll
        for (int i = 0; i < 8; i++) { acc2[i][0] = 0ull; acc2[i][1] = 0ull; }

        #pragma unroll
        for (int h = 0; h < 2; h++) {
            ull accA[8][2];
            #pragma unroll
            for (int i = 0; i < 8; i++) { accA[i][0] = 0ull; accA[i][1] = 0ull; }
            #pragma unroll
            for (int k0 = 0; k0 < 16; k0 += 4) {
                ulonglong2 w0 = *(const ulonglong2*)(sWe1 + (k0 + 0) * 256 + h * 128 + jj);
                ulonglong2 w1 = *(const ulonglong2*)(sWe1 + (k0 + 1) * 256 + h * 128 + jj);
                ulonglong2 w2 = *(const ulonglong2*)(sWe1 + (k0 + 2) * 256 + h * 128 + jj);
                ulonglong2 w3 = *(const ulonglong2*)(sWe1 + (k0 + 3) * 256 + h * 128 + jj);
                #pragma unroll
                for (int i = 0; i < 8; i++) {
                    float4 a4 = *(const float4*)(myX + i * 16 + k0);
                    ull ax = pk2(a4.x), ay = pk2(a4.y), az = pk2(a4.z), aw = pk2(a4.w);
                    ffma2(accA[i][0], ax, w0.x); ffma2(accA[i][1], ax, w0.y);
                    ffma2(accA[i][0], ay, w1.x); ffma2(accA[i][1], ay, w1.y);
                    ffma2(accA[i][0], az, w2.x); ffma2(accA[i][1], az, w2.y);
                    ffma2(accA[i][0], aw, w3.x); ffma2(accA[i][1], aw, w3.y);
                }
            }
            {
                float4 b = *(const float4*)(sbe1 + h * 128 + jj);
                #pragma unroll
                for (int i = 0; i < 8; i++) {
                    float2 t0 = up2(accA[i][0]), t1 = up2(accA[i][1]);
                    float4 r;
                    r.x = fmaxf(t0.x + b.x, 0.f); r.y = fmaxf(t0.y + b.y, 0.f);
                    r.z = fmaxf(t1.x + b.z, 0.f); r.w = fmaxf(t1.y + b.w, 0.f);
                    *(float4*)(myE1 + i * 128 + jj) = r;
                    cs1[h][0] += r.x; cs1[h][1] += r.y; cs1[h][2] += r.z; cs1[h][3] += r.w;
                    int rI = __shfl_sync(0xffffffffu, idxreg, 8 + i);
                    int sI = __shfl_sync(0xffffffffu, idxreg, i);
                    float fI = __shfl_sync(0xffffffffu, sclreg, 8 + i);
                    float fO = __shfl_sync(0xffffffffu, sclreg, i);
                    red4(g_inc1 + (long)rI * 256 + h * 128 + jj,
                         r.x * fI, r.y * fI, r.z * fI, r.w * fI);
                    red4(g_out1 + (long)sI * 256 + h * 128 + jj,
                         r.x * fO, r.y * fO, r.z * fO, r.w * fO);
                }
            }
            __syncwarp();

            #pragma unroll 4
            for (int k0 = 0; k0 < 128; k0 += 4) {
                ulonglong2 w0 = *(const ulonglong2*)(sWe2 + (h * 128 + k0 + 0) * 128 + jj);
                ulonglong2 w1 = *(const ulonglong2*)(sWe2 + (h * 128 + k0 + 1) * 128 + jj);
                ulonglong2 w2 = *(const ulonglong2*)(sWe2 + (h * 128 + k0 + 2) * 128 + jj);
                ulonglong2 w3 = *(const ulonglong2*)(sWe2 + (h * 128 + k0 + 3) * 128 + jj);
                #pragma unroll
                for (int i = 0; i < 8; i++) {
                    float4 a4 = *(const float4*)(myE1 + i * 128 + k0);
                    ull ax = pk2(a4.x), ay = pk2(a4.y), az = pk2(a4.z), aw = pk2(a4.w);
                    ffma2(acc2[i][0], ax, w0.x); ffma2(acc2[i][1], ax, w0.y);
                    ffma2(acc2[i][0], ay, w1.x); ffma2(acc2[i][1], ay, w1.y);
                    ffma2(acc2[i][0], az, w2.x); ffma2(acc2[i][1], az, w2.y);
                    ffma2(acc2[i][0], aw, w3.x); ffma2(acc2[i][1], aw, w3.y);
                }
            }
            __syncwarp();
        }

        {
            float4 b = *(const float4*)(sbe2 + jj);
            #pragma unroll
            for (int i = 0; i < 8; i++) {
                float2 t0 = up2(acc2[i][0]), t1 = up2(acc2[i][1]);
                float4 r;
                r.x = fmaxf(t0.x + b.x, 0.f); r.y = fmaxf(t0.y + b.y, 0.f);
                r.z = fmaxf(t1.x + b.z, 0.f); r.w = fmaxf(t1.y + b.w, 0.f);
                *(float4*)(e2_out + (base + i) * 128 + jj) = r;
                cs2[0] += r.x; cs2[1] += r.y; cs2[2] += r.z; cs2[3] += r.w;
                int rI = __shfl_sync(0xffffffffu, idxreg, 8 + i);
                int sI = __shfl_sync(0xffffffffu, idxreg, i);
                float fI = __shfl_sync(0xffffffffu, sclreg, 8 + i);
                float fO = __shfl_sync(0xffffffffu, sclreg, i);
                red4(g_inc2 + (long)rI * 128 + jj,
                     r.x * fI, r.y * fI, r.z * fI, r.w * fI);
                red4(g_out2 + (long)sI * 128 + jj,
                     r.x * fO, r.y * fO, r.z * fO, r.w * fO);
            }
        }
        if (lane == 0) grp = atomicAdd(&g_tick[0], 1);
        grp = __shfl_sync(0xffffffffu, grp, 0);
    }
    red4(g_scr + OFF_E1SUM + jj,       cs1[0][0], cs1[0][1], cs1[0][2], cs1[0][3]);
    red4(g_scr + OFF_E1SUM + 128 + jj, cs1[1][0], cs1[1][1], cs1[1][2], cs1[1][3]);
    red4(g_scr + OFF_E2SUM + jj,       cs2[0], cs2[1], cs2[2], cs2[3]);
}

// ---------------- fused node kernel (ticketed tiles, k32 W-only GEMM2 phase) -
#define K2_TILES 782
#define NC1 34
#define NC2 24   /* 8 x k32 (sN1 phase) + 16 x k16 (gather phase) */

__device__ __forceinline__ void g1_issue(int c, int base, float* sWb, float* sAb,
        const float* Wn1, const float* Win1, const float* Wout1,
        const float* nodes, const float* inc1, const float* out1,
        int tid, int an, int aq)
{
    const float* Wsrc; int kb;
    if (c < 2)       { Wsrc = Wn1;   kb = c * 16; }
    else if (c < 18) { Wsrc = Win1;  kb = (c - 2) * 16; }
    else             { Wsrc = Wout1; kb = (c - 18) * 16; }
    uint32_t wdst = s2u(sWb);
    #pragma unroll
    for (int r = 0; r < 4; r++) {
        int q = tid + r * 256;
        int k = q >> 6, j = (q & 63) * 4;
        cpa16(wdst + (uint32_t)(k * 256 + j) * 4, Wsrc + (long)(kb + k) * 256 + j);
    }
    int node = base + an;
    uint32_t adst = s2u(sAb) + (uint32_t)(an * 16 + aq) * 4;
    if (c < 2) {
        int ns = node < NN ? node : NN - 1;
        cpa16z(adst, nodes + (long)ns * 32 + c * 16 + aq, node < NN);
    } else if (c < 18) {
        cpa16(adst, inc1 + (long)node * 256 + (c - 2) * 16 + aq);
    } else {
        cpa16(adst, out1 + (long)node * 256 + (c - 18) * 16 + aq);
    }
}

// GEMM2 chunks: c in [0,8): k=32 from Wn2 (W-only);
//               c in [8,24): k=16 gather (Win2/inc2 then Wout2/out2).
__device__ __forceinline__ void g2_issue(int c, int base, float* sWb, float* sAb,
        const float* Wn2, const float* Win2, const float* Wout2,
        const float* inc2, const float* out2,
        int tid, int an, int aq)
{
    uint32_t wdst = s2u(sWb);
    if (c < 8) {
        // 32x128 = 4096 floats: 4 cpa16 per thread
        #pragma unroll
        for (int r = 0; r < 4; r++) {
            int q = tid + r * 256;
            int k = q >> 5, j = (q & 31) * 4;
            cpa16(wdst + (uint32_t)(k * 128 + j) * 4, Wn2 + (long)(c * 32 + k) * 128 + j);
        }
    } else {
        const float* Wsrc; int kb;
        int c2 = c - 8;
        if (c2 < 8) { Wsrc = Win2;  kb = c2 * 16; }
        else        { Wsrc = Wout2; kb = (c2 - 8) * 16; }
        #pragma unroll
        for (int r = 0; r < 2; r++) {
            int q = tid + r * 256;
            int k = q >> 5, j = (q & 31) * 4;
            cpa16(wdst + (uint32_t)(k * 128 + j) * 4, Wsrc + (long)(kb + k) * 128 + j);
        }
        int node = base + an;
        uint32_t adst = s2u(sAb) + (uint32_t)(an * 16 + aq) * 4;
        if (c2 < 8) cpa16(adst, inc2 + (long)node * 128 + c2 * 16 + aq);
        else        cpa16(adst, out2 + (long)node * 128 + (c2 - 8) * 16 + aq);
    }
}

__global__ void __launch_bounds__(256, 2) k_nodes(
    const float* __restrict__ nodes,
    const float* __restrict__ Wn1, const float* __restrict__ Win1,
    const float* __restrict__ Wout1, const float* __restrict__ bn1,
    const float* __restrict__ Wn2, const float* __restrict__ Win2,
    const float* __restrict__ Wout2, const float* __restrict__ bn2,
    float* __restrict__ n2_out)
{
    extern __shared__ float sm[];
    float* sN1  = sm;                       // 16384
    float* sW0  = sN1 + 16384;              // 4096
    float* sW1  = sW0 + 4096;               // 4096
    float* sA0  = sW1 + 4096;               // 1024
    float* sA1  = sA0 + 1024;               // 1024
    float* sbn1 = sA1 + 1024;               // 256
    float* sbn2 = sbn1 + 256;               // 128
    int*   sTile = (int*)(sbn2 + 128);      // 1 int
    // total = 27009 floats ~= 108040 B (2 CTAs/SM)

    const int tid = threadIdx.x;
    if (tid < 256) sbn1[tid] = bn1[tid];
    if (tid < 128) sbn2[tid] = bn2[tid];

    const int ig  = tid >> 5;
    const int jg  = tid & 31;
    const int n0  = ig * 8;
    const int jja = jg * 4;            // GEMM1 half A cols
    const int jjb = 128 + jg * 4;      // GEMM1 half B cols
    const int jj2 = jg * 4;            // GEMM2 cols
    const int an  = tid >> 2;
    const int aq  = (tid & 3) * 4;

    float csn1[8] = {0.f,0.f,0.f,0.f,0.f,0.f,0.f,0.f};
    float csn2[4] = {0.f,0.f,0.f,0.f};

    const float* g_inc1 = g_scr + OFF_INC1;
    const float* g_out1 = g_scr + OFF_OUT1;
    const float* g_inc2 = g_scr + OFF_INC2;
    const float* g_out2 = g_scr + OFF_OUT2;

    while (true) {
        // ---- dynamic tile ticket ----
        if (tid == 0) *sTile = atomicAdd(&g_tick[1], 1);
        __syncthreads();
        const int tile = *sTile;
        if (tile >= K2_TILES) break;
        const int base = tile * 64;

        // ================= GEMM1: 34 chunks of 16 k, double-buffered =========
        ull acc1[8][4];
        #pragma unroll
        for (int i = 0; i < 8; i++)
            #pragma unroll
            for (int q = 0; q < 4; q++) acc1[i][q] = 0ull;

        g1_issue(0, base, sW0, sA0, Wn1, Win1, Wout1, nodes, g_inc1, g_out1, tid, an, aq);
        CPA_COMMIT();
        for (int c = 0; c < NC1; c++) {
            float* sWb = (c & 1) ? sW1 : sW0;
            float* sAb = (c & 1) ? sA1 : sA0;
            if (c + 1 < NC1) {
                g1_issue(c + 1, base, (c & 1) ? sW0 : sW1, (c & 1) ? sA0 : sA1,
                         Wn1, Win1, Wout1, nodes, g_inc1, g_out1, tid, an, aq);
                CPA_COMMIT();
                CPA_WAIT1();
            } else {
                CPA_WAIT0();
            }
            __syncthreads();
            #pragma unroll 2
            for (int k = 0; k < 16; k++) {
                ulonglong2 wA = *(const ulonglong2*)(sWb + k * 256 + jja);
                ulonglong2 wB = *(const ulonglong2*)(sWb + k * 256 + jjb);
                #pragma unroll
                for (int i = 0; i < 8; i++) {
                    ull a = pk2(sAb[(n0 + i) * 16 + k]);
                    ffma2(acc1[i][0], a, wA.x);
                    ffma2(acc1[i][1], a, wA.y);
                    ffma2(acc1[i][2], a, wB.x);
                    ffma2(acc1[i][3], a, wB.y);
                }
            }
            __syncthreads();
        }
        // epilogue: n1 -> sN1 (+colsum)
        {
            float4 b0 = *(const float4*)(sbn1 + jja);
            float4 b1 = *(const float4*)(sbn1 + jjb);
            #pragma unroll
            for (int i = 0; i < 8; i++) {
                bool valid = (base + n0 + i) < NN;
                float2 t0 = up2(acc1[i][0]), t1 = up2(acc1[i][1]);
                float2 t2 = up2(acc1[i][2]), t3 = up2(acc1[i][3]);
                float4 r0, r1;
                r0.x = valid ? fmaxf(t0.x + b0.x, 0.f) : 0.f;
                r0.y = valid ? fmaxf(t0.y + b0.y, 0.f) : 0.f;
                r0.z = valid ? fmaxf(t1.x + b0.z, 0.f) : 0.f;
                r0.w = valid ? fmaxf(t1.y + b0.w, 0.f) : 0.f;
                r1.x = valid ? fmaxf(t2.x + b1.x, 0.f) : 0.f;
                r1.y = valid ? fmaxf(t2.y + b1.y, 0.f) : 0.f;
                r1.z = valid ? fmaxf(t3.x + b1.z, 0.f) : 0.f;
                r1.w = valid ? fmaxf(t3.y + b1.w, 0.f) : 0.f;
                *(float4*)(sN1 + (n0 + i) * 256 + jja) = r0;
                *(float4*)(sN1 + (n0 + i) * 256 + jjb) = r1;
                csn1[0] += r0.x; csn1[1] += r0.y; csn1[2] += r0.z; csn1[3] += r0.w;
                csn1[4] += r1.x; csn1[5] += r1.y; csn1[6] += r1.z; csn1[7] += r1.w;
            }
        }

        // ================= GEMM2: 8 x k32 (sN1) + 16 x k16 (gather) ==========
        ull acc2[8][2];
        #pragma unroll
        for (int i = 0; i < 8; i++) { acc2[i][0] = 0ull; acc2[i][1] = 0ull; }

        g2_issue(0, base, sW0, sA0, Wn2, Win2, Wout2, g_inc2, g_out2, tid, an, aq);
        CPA_COMMIT();
        for (int c = 0; c < NC2; c++) {
            float* sWb = (c & 1) ? sW1 : sW0;
            float* sAb = (c & 1) ? sA1 : sA0;
            if (c + 1 < NC2) {
                g2_issue(c + 1, base, (c & 1) ? sW0 : sW1, (c & 1) ? sA0 : sA1,
                         Wn2, Win2, Wout2, g_inc2, g_out2, tid, an, aq);
                CPA_COMMIT();
                CPA_WAIT1();
            } else {
                CPA_WAIT0();
            }
            __syncthreads();   // chunk c ready; also orders sN1 epilogue writes
            if (c < 8) {
                #pragma unroll 2
                for (int k = 0; k < 32; k++) {
                    ulonglong2 w = *(const ulonglong2*)(sWb + k * 128 + jj2);
                    #pragma unroll
                    for (int i = 0; i < 8; i++) {
                        ull a = pk2(sN1[(n0 + i) * 256 + c * 32 + k]);
                        ffma2(acc2[i][0], a, w.x);
                        ffma2(acc2[i][1], a, w.y);
                    }
                }
            } else {
                #pragma unroll 2
                for (int k = 0; k < 16; k++) {
                    ulonglong2 w = *(const ulonglong2*)(sWb + k * 128 + jj2);
                    #pragma unroll
                    for (int i = 0; i < 8; i++) {
                        ull a = pk2(sAb[(n0 + i) * 16 + k]);
                        ffma2(acc2[i][0], a, w.x);
                        ffma2(acc2[i][1], a, w.y);
                    }
                }
            }
            __syncthreads();
        }
        // epilogue: n2 -> global (+colsum)
        {
            float4 b0 = *(const float4*)(sbn2 + jj2);
            #pragma unroll
            for (int i = 0; i < 8; i++) {
                int node = base + n0 + i;
                if (node < NN) {
                    float2 t0 = up2(acc2[i][0]), t1 = up2(acc2[i][1]);
                    float4 r0;
                    r0.x = fmaxf(t0.x + b0.x, 0.f);
                    r0.y = fmaxf(t0.y + b0.y, 0.f);
                    r0.z = fmaxf(t1.x + b0.z, 0.f);
                    r0.w = fmaxf(t1.y + b0.w, 0.f);
                    *(float4*)(n2_out + (long)node * 128 + jj2) = r0;
                    csn2[0] += r0.x; csn2[1] += r0.y; csn2[2] += r0.z; csn2[3] += r0.w;
                }
            }
        }
    }
    red4(g_scr + OFF_N1SUM + jja, csn1[0], csn1[1], csn1[2], csn1[3]);
    red4(g_scr + OFF_N1SUM + jjb, csn1[4], csn1[5], csn1[6], csn1[7]);
    red4(g_scr + OFF_N2SUM + jj2, csn2[0], csn2[1], csn2[2], csn2[3]);
}

// ---------------- globals kernel ----------------
__global__ void k_glob(
    const float* __restrict__ gu,
    const float* __restrict__ Wu1, const float* __restrict__ Wgn1,
    const float* __restrict__ Wge1, const float* __restrict__ bu1,
    const float* __restrict__ Wu2, const float* __restrict__ Wgn2,
    const float* __restrict__ Wge2, const float* __restrict__ bu2,
    float* __restrict__ u2_out)
{
    __shared__ float su1[256];
    __shared__ float sgu[16];
    __shared__ float sn1m[256], se1m[256];
    const int tid = threadIdx.x;
    if (tid < 16) sgu[tid] = gu[tid];
    sn1m[tid] = g_scr[OFF_N1SUM + tid] * (1.0f / NN);
    se1m[tid] = g_scr[OFF_E1SUM + tid] * (1.0f / EE);
    __syncthreads();
    {
        float s = bu1[tid];
        #pragma unroll 4
        for (int k = 0; k < 16; k++) s = fmaf(sgu[k], Wu1[k * 256 + tid], s);
        #pragma unroll 4
        for (int k = 0; k < 256; k++) {
            s = fmaf(sn1m[k], Wgn1[k * 256 + tid], s);
            s = fmaf(se1m[k], Wge1[k * 256 + tid], s);
        }
        su1[tid] = fmaxf(s, 0.f);
    }
    __syncthreads();
    if (tid < 128) {
        float s = bu2[tid];
        #pragma unroll 4
        for (int k = 0; k < 256; k++) s = fmaf(su1[k], Wu2[k * 128 + tid], s);
        #pragma unroll 4
        for (int k = 0; k < 128; k++) {
            s = fmaf(g_scr[OFF_N2SUM + k] * (1.0f / NN), Wgn2[k * 128 + tid], s);
            s = fmaf(g_scr[OFF_E2SUM + k] * (1.0f / EE), Wge2[k * 128 + tid], s);
        }
        u2_out[tid] = fmaxf(s, 0.f);
    }
}

extern "C" void kernel_launch(void* const* d_in, const int* in_sizes, int n_in,
                              void* d_out, int out_size) {
    const float* nodes = (const float*)d_in[0];
    const float* edges = (const float*)d_in[1];
    const float* gu    = (const float*)d_in[2];
    const int*   snd   = (const int*)d_in[3];
    const int*   rcv   = (const int*)d_in[4];
    const float* We1 = (const float*)d_in[5];
    const float* be1 = (const float*)d_in[6];
    const float* Wn1 = (const float*)d_in[7];
    const float* Win1 = (const float*)d_in[8];
    const float* Wout1 = (const float*)d_in[9];
    const float* bn1 = (const float*)d_in[10];
    const float* Wu1 = (const float*)d_in[11];
    const float* Wgn1 = (const float*)d_in[12];
    const float* Wge1 = (const float*)d_in[13];
    const float* bu1 = (const float*)d_in[14];
    const float* We2 = (const float*)d_in[15];
    const float* be2 = (const float*)d_in[16];
    const float* Wn2 = (const float*)d_in[17];
    const float* Win2 = (const float*)d_in[18];
    const float* Wout2 = (const float*)d_in[19];
    const float* bn2 = (const float*)d_in[20];
    const float* Wu2 = (const float*)d_in[21];
    const float* Wgn2 = (const float*)d_in[22];
    const float* Wge2 = (const float*)d_in[23];
    const float* bu2 = (const float*)d_in[24];

    float* out    = (float*)d_out;
    float* n2_out = out;
    float* e2_out = out + (long)NN * H2;                       // 6,400,000
    float* u2_out = out + (long)NN * H2 + (long)EE * H2;       // 57,600,000

    const int SMEM_K1 = (32768 + 4096 + 12288 + 1536 + 256 + 128) * 4;   // 204288
    const int SMEM_K2 = (16384 + 4096 + 4096 + 1024 + 1024 + 256 + 128 + 4) * 4; // 108048
    cudaFuncSetAttribute(k_edges, cudaFuncAttributeMaxDynamicSharedMemorySize, SMEM_K1);
    cudaFuncSetAttribute(k_nodes, cudaFuncAttributeMaxDynamicSharedMemorySize, SMEM_K2);

    k_zero<<<(ZERO_FLOATS / 4 + 255) / 256, 256>>>();
    k_deg<<<(EE + 255) / 256, 256>>>(snd, rcv);
    k_inv<<<(NN + 255) / 256, 256>>>();
    k_edges<<<148, NT, SMEM_K1>>>(edges, snd, rcv, We1, be1, We2, be2, e2_out);
    k_nodes<<<296, 256, SMEM_K2>>>(nodes, Wn1, Win1, Wout1, bn1,
                                   Wn2, Win2, Wout2, bn2, n2_out);
    k_glob<<<1, 256>>>(gu, Wu1, Wgn1, Wge1, bu1, Wu2, Wgn2, Wge2, bu2, u2_out);
}

// round 12
// speedup vs baseline: 1.1665x; 1.1009x over previous
#include <cuda_runtime.h>
#include <cstdint>

#define NN 50000
#define EE 400000
#define H1 256
#define H2 128

// ---- scratch layout (floats) ----
#define OFF_INC1   0                       // N*256
#define OFF_OUT1   12800000                // N*256
#define OFF_INC2   25600000                // N*128
#define OFF_OUT2   32000000                // N*128
#define OFF_E1SUM  38400000                // 256
#define OFF_E2SUM  38400256                // 128
#define OFF_N1SUM  38400384                // 256
#define OFF_N2SUM  38400640                // 128
#define OFF_INVIN  38400768                // N
#define OFF_INVOUT 38450768                // N
#define SCR_TOTAL  38500864
#define ZERO_FLOATS 38400768               // [0, OFF_INVIN) must be zeroed

__device__ float g_scr[SCR_TOTAL];
__device__ int   g_cnt[2 * NN];
__device__ int   g_tick[2];                // [0]=edge groups, [1]=node tiles

typedef unsigned long long ull;

__device__ __forceinline__ void red4(float* p, float a, float b, float c, float d) {
    asm volatile("red.global.add.v4.f32 [%0], {%1,%2,%3,%4};"
                 :: "l"(p), "f"(a), "f"(b), "f"(c), "f"(d) : "memory");
}
__device__ __forceinline__ ull pk2(float x) {
    ull r; asm("mov.b64 %0, {%1, %1};" : "=l"(r) : "f"(x)); return r;
}
__device__ __forceinline__ void ffma2(ull& acc, ull a, ull b) {
    asm("fma.rn.f32x2 %0, %1, %2, %0;" : "+l"(acc) : "l"(a), "l"(b));
}
__device__ __forceinline__ float2 up2(ull v) {
    float2 f; asm("mov.b64 {%0, %1}, %2;" : "=f"(f.x), "=f"(f.y) : "l"(v)); return f;
}
__device__ __forceinline__ uint32_t s2u(const void* p) {
    return (uint32_t)__cvta_generic_to_shared(p);
}
__device__ __forceinline__ void cpa16(uint32_t dst, const void* src) {
    asm volatile("cp.async.cg.shared.global [%0], [%1], 16;" :: "r"(dst), "l"(src));
}
__device__ __forceinline__ void cpa16z(uint32_t dst, const void* src, int ok) {
    asm volatile("cp.async.cg.shared.global [%0], [%1], 16, %2;"
                 :: "r"(dst), "l"(src), "r"(ok ? 16 : 0));
}
#define CPA_COMMIT() asm volatile("cp.async.commit_group;" ::: "memory")
#define CPA_WAIT1()  asm volatile("cp.async.wait_group 1;" ::: "memory")
#define CPA_WAIT0()  asm volatile("cp.async.wait_group 0;" ::: "memory")

// ---------------- zero scratch + tickets ----------------
__global__ void k_zero() {
    long i = (long)blockIdx.x * 256 + threadIdx.x;
    if (i < ZERO_FLOATS / 4) {
        float4 z = {0.f, 0.f, 0.f, 0.f};
        *(float4*)(g_scr + i * 4) = z;
    }
    if (i < (2 * NN) / 4) {
        int4 z = {0, 0, 0, 0};
        *(int4*)(g_cnt + i * 4) = z;
    }
    if (i == 0) { g_tick[0] = 0; g_tick[1] = 0; }
}

// ---------------- degrees ----------------
__global__ void k_deg(const int* __restrict__ snd, const int* __restrict__ rcv) {
    int i = blockIdx.x * 256 + threadIdx.x;
    if (i < EE) {
        atomicAdd(&g_cnt[rcv[i]], 1);
        atomicAdd(&g_cnt[NN + snd[i]], 1);
    }
}

__global__ void k_inv() {
    int i = blockIdx.x * 256 + threadIdx.x;
    if (i < NN) {
        int ci = g_cnt[i];      g_scr[OFF_INVIN  + i] = 1.0f / (float)(ci > 1 ? ci : 1);
        int co = g_cnt[NN + i]; g_scr[OFF_INVOUT + i] = 1.0f / (float)(co > 1 ? co : 1);
    }
}

// ---------------- fused edge kernel (12 warps, 8 rows/warp, ticketed) --------
#define GRPS 50000   /* EE / 8 */
#define NWARP 12
#define NT 384
__global__ void __launch_bounds__(NT, 1) k_edges(
    const float* __restrict__ edges, const int* __restrict__ snd, const int* __restrict__ rcv,
    const float* __restrict__ We1, const float* __restrict__ be1,
    const float* __restrict__ We2, const float* __restrict__ be2,
    float* __restrict__ e2_out)
{
    extern __shared__ float sm[];
    float* sWe2 = sm;                 // 256*128 = 32768
    float* sWe1 = sWe2 + 32768;       // 16*256  = 4096
    float* sE1  = sWe1 + 4096;        // 12 warps * 8*128 = 12288
    float* sX   = sE1 + 12288;        // 12 warps * 8*16  = 1536
    float* sbe1 = sX + 1536;          // 256
    float* sbe2 = sbe1 + 256;         // 128

    const int tid = threadIdx.x;
    for (int i = tid; i < 32768; i += NT) sWe2[i] = We2[i];
    for (int i = tid; i < 4096;  i += NT) sWe1[i] = We1[i];
    if (tid < 256) sbe1[tid] = be1[tid];
    else           sbe2[tid - 256] = be2[tid - 256];
    __syncthreads();

    const int wid  = tid >> 5;
    const int lane = tid & 31;
    float* myE1 = sE1 + wid * 1024;   // 8 rows x 128
    float* myX  = sX  + wid * 128;    // 8 rows x 16
    const int jj = lane * 4;

    float cs1[2][4] = {{0.f,0.f,0.f,0.f},{0.f,0.f,0.f,0.f}};
    float cs2[4] = {0.f,0.f,0.f,0.f};

    float* g_inc1 = g_scr + OFF_INC1;
    float* g_out1 = g_scr + OFF_OUT1;
    float* g_inc2 = g_scr + OFF_INC2;
    float* g_out2 = g_scr + OFF_OUT2;

    const int le = lane >> 2, lq = lane & 3;   // X fill mapping

    int grp;
    if (lane == 0) grp = atomicAdd(&g_tick[0], 1);
    grp = __shfl_sync(0xffffffffu, grp, 0);

    while (grp < GRPS) {
        const long base = (long)grp * 8;
        __syncwarp();
        *(float4*)(myX + le * 16 + lq * 4) =
            *(const float4*)(edges + (base + le) * 16 + lq * 4);
        int idxreg = 0; float sclreg = 0.f;
        if (lane < 8) {
            idxreg = snd[base + lane];
            sclreg = g_scr[OFF_INVOUT + idxreg];
        } else if (lane < 16) {
            idxreg = rcv[base + lane - 8];
            sclreg = g_scr[OFF_INVIN + idxreg];
        }
        __syncwarp();

        ull acc2[8][2];
        #pragma unroll
        for (int i = 0; i < 8; i++) { acc2[i][0] = 0ull; acc2[i][1] = 0ull; }

        #pragma unroll
        for (int h = 0; h < 2; h++) {
            ull accA[8][2];
            #pragma unroll
            for (int i = 0; i < 8; i++) { accA[i][0] = 0ull; accA[i][1] = 0ull; }
            #pragma unroll
            for (int k0 = 0; k0 < 16; k0 += 4) {
                ulonglong2 w0 = *(const ulonglong2*)(sWe1 + (k0 + 0) * 256 + h * 128 + jj);
                ulonglong2 w1 = *(const ulonglong2*)(sWe1 + (k0 + 1) * 256 + h * 128 + jj);
                ulonglong2 w2 = *(const ulonglong2*)(sWe1 + (k0 + 2) * 256 + h * 128 + jj);
                ulonglong2 w3 = *(const ulonglong2*)(sWe1 + (k0 + 3) * 256 + h * 128 + jj);
                #pragma unroll
                for (int i = 0; i < 8; i++) {
                    float4 a4 = *(const float4*)(myX + i * 16 + k0);
                    ull ax = pk2(a4.x), ay = pk2(a4.y), az = pk2(a4.z), aw = pk2(a4.w);
                    ffma2(accA[i][0], ax, w0.x); ffma2(accA[i][1], ax, w0.y);
                    ffma2(accA[i][0], ay, w1.x); ffma2(accA[i][1], ay, w1.y);
                    ffma2(accA[i][0], az, w2.x); ffma2(accA[i][1], az, w2.y);
                    ffma2(accA[i][0], aw, w3.x); ffma2(accA[i][1], aw, w3.y);
                }
            }
            {
                float4 b = *(const float4*)(sbe1 + h * 128 + jj);
                #pragma unroll
                for (int i = 0; i < 8; i++) {
                    float2 t0 = up2(accA[i][0]), t1 = up2(accA[i][1]);
                    float4 r;
                    r.x = fmaxf(t0.x + b.x, 0.f); r.y = fmaxf(t0.y + b.y, 0.f);
                    r.z = fmaxf(t1.x + b.z, 0.f); r.w = fmaxf(t1.y + b.w, 0.f);
                    *(float4*)(myE1 + i * 128 + jj) = r;
                    cs1[h][0] += r.x; cs1[h][1] += r.y; cs1[h][2] += r.z; cs1[h][3] += r.w;
                    int rI = __shfl_sync(0xffffffffu, idxreg, 8 + i);
                    int sI = __shfl_sync(0xffffffffu, idxreg, i);
                    float fI = __shfl_sync(0xffffffffu, sclreg, 8 + i);
                    float fO = __shfl_sync(0xffffffffu, sclreg, i);
                    red4(g_inc1 + (long)rI * 256 + h * 128 + jj,
                         r.x * fI, r.y * fI, r.z * fI, r.w * fI);
                    red4(g_out1 + (long)sI * 256 + h * 128 + jj,
                         r.x * fO, r.y * fO, r.z * fO, r.w * fO);
                }
            }
            __syncwarp();

            #pragma unroll 4
            for (int k0 = 0; k0 < 128; k0 += 4) {
                ulonglong2 w0 = *(const ulonglong2*)(sWe2 + (h * 128 + k0 + 0) * 128 + jj);
                ulonglong2 w1 = *(const ulonglong2*)(sWe2 + (h * 128 + k0 + 1) * 128 + jj);
                ulonglong2 w2 = *(const ulonglong2*)(sWe2 + (h * 128 + k0 + 2) * 128 + jj);
                ulonglong2 w3 = *(const ulonglong2*)(sWe2 + (h * 128 + k0 + 3) * 128 + jj);
                #pragma unroll
                for (int i = 0; i < 8; i++) {
                    float4 a4 = *(const float4*)(myE1 + i * 128 + k0);
                    ull ax = pk2(a4.x), ay = pk2(a4.y), az = pk2(a4.z), aw = pk2(a4.w);
                    ffma2(acc2[i][0], ax, w0.x); ffma2(acc2[i][1], ax, w0.y);
                    ffma2(acc2[i][0], ay, w1.x); ffma2(acc2[i][1], ay, w1.y);
                    ffma2(acc2[i][0], az, w2.x); ffma2(acc2[i][1], az, w2.y);
                    ffma2(acc2[i][0], aw, w3.x); ffma2(acc2[i][1], aw, w3.y);
                }
            }
            __syncwarp();
        }

        {
            float4 b = *(const float4*)(sbe2 + jj);
            #pragma unroll
            for (int i = 0; i < 8; i++) {
                float2 t0 = up2(acc2[i][0]), t1 = up2(acc2[i][1]);
                float4 r;
                r.x = fmaxf(t0.x + b.x, 0.f); r.y = fmaxf(t0.y + b.y, 0.f);
                r.z = fmaxf(t1.x + b.z, 0.f); r.w = fmaxf(t1.y + b.w, 0.f);
                *(float4*)(e2_out + (base + i) * 128 + jj) = r;
                cs2[0] += r.x; cs2[1] += r.y; cs2[2] += r.z; cs2[3] += r.w;
                int rI = __shfl_sync(0xffffffffu, idxreg, 8 + i);
                int sI = __shfl_sync(0xffffffffu, idxreg, i);
                float fI = __shfl_sync(0xffffffffu, sclreg, 8 + i);
                float fO = __shfl_sync(0xffffffffu, sclreg, i);
                red4(g_inc2 + (long)rI * 128 + jj,
                     r.x * fI, r.y * fI, r.z * fI, r.w * fI);
                red4(g_out2 + (long)sI * 128 + jj,
                     r.x * fO, r.y * fO, r.z * fO, r.w * fO);
            }
        }
        if (lane == 0) grp = atomicAdd(&g_tick[0], 1);
        grp = __shfl_sync(0xffffffffu, grp, 0);
    }
    red4(g_scr + OFF_E1SUM + jj,       cs1[0][0], cs1[0][1], cs1[0][2], cs1[0][3]);
    red4(g_scr + OFF_E1SUM + 128 + jj, cs1[1][0], cs1[1][1], cs1[1][2], cs1[1][3]);
    red4(g_scr + OFF_E2SUM + jj,       cs2[0], cs2[1], cs2[2], cs2[3]);
}

// ---------------- fused node kernel (float4 a-loads, 4k-blocked) -------------
#define K2_TILES 782
#define NC1 34
#define NC2 24   /* 8 x k32 (sN1 phase) + 16 x k16 (gather phase) */

__device__ __forceinline__ void g1_issue(int c, int base, float* sWb, float* sAb,
        const float* Wn1, const float* Win1, const float* Wout1,
        const float* nodes, const float* inc1, const float* out1,
        int tid, int an, int aq)
{
    const float* Wsrc; int kb;
    if (c < 2)       { Wsrc = Wn1;   kb = c * 16; }
    else if (c < 18) { Wsrc = Win1;  kb = (c - 2) * 16; }
    else             { Wsrc = Wout1; kb = (c - 18) * 16; }
    uint32_t wdst = s2u(sWb);
    #pragma unroll
    for (int r = 0; r < 4; r++) {
        int q = tid + r * 256;
        int k = q >> 6, j = (q & 63) * 4;
        cpa16(wdst + (uint32_t)(k * 256 + j) * 4, Wsrc + (long)(kb + k) * 256 + j);
    }
    int node = base + an;
    uint32_t adst = s2u(sAb) + (uint32_t)(an * 16 + aq) * 4;
    if (c < 2) {
        int ns = node < NN ? node : NN - 1;
        cpa16z(adst, nodes + (long)ns * 32 + c * 16 + aq, node < NN);
    } else if (c < 18) {
        cpa16(adst, inc1 + (long)node * 256 + (c - 2) * 16 + aq);
    } else {
        cpa16(adst, out1 + (long)node * 256 + (c - 18) * 16 + aq);
    }
}

__device__ __forceinline__ void g2_issue(int c, int base, float* sWb, float* sAb,
        const float* Wn2, const float* Win2, const float* Wout2,
        const float* inc2, const float* out2,
        int tid, int an, int aq)
{
    uint32_t wdst = s2u(sWb);
    if (c < 8) {
        #pragma unroll
        for (int r = 0; r < 4; r++) {
            int q = tid + r * 256;
            int k = q >> 5, j = (q & 31) * 4;
            cpa16(wdst + (uint32_t)(k * 128 + j) * 4, Wn2 + (long)(c * 32 + k) * 128 + j);
        }
    } else {
        const float* Wsrc; int kb;
        int c2 = c - 8;
        if (c2 < 8) { Wsrc = Win2;  kb = c2 * 16; }
        else        { Wsrc = Wout2; kb = (c2 - 8) * 16; }
        #pragma unroll
        for (int r = 0; r < 2; r++) {
            int q = tid + r * 256;
            int k = q >> 5, j = (q & 31) * 4;
            cpa16(wdst + (uint32_t)(k * 128 + j) * 4, Wsrc + (long)(kb + k) * 128 + j);
        }
        int node = base + an;
        uint32_t adst = s2u(sAb) + (uint32_t)(an * 16 + aq) * 4;
        if (c2 < 8) cpa16(adst, inc2 + (long)node * 128 + c2 * 16 + aq);
        else        cpa16(adst, out2 + (long)node * 128 + (c2 - 8) * 16 + aq);
    }
}

__global__ void __launch_bounds__(256, 2) k_nodes(
    const float* __restrict__ nodes,
    const float* __restrict__ Wn1, const float* __restrict__ Win1,
    const float* __restrict__ Wout1, const float* __restrict__ bn1,
    const float* __restrict__ Wn2, const float* __restrict__ Win2,
    const float* __restrict__ Wout2, const float* __restrict__ bn2,
    float* __restrict__ n2_out)
{
    extern __shared__ float sm[];
    float* sN1  = sm;                       // 16384
    float* sW0  = sN1 + 16384;              // 4096
    float* sW1  = sW0 + 4096;               // 4096
    float* sA0  = sW1 + 4096;               // 1024
    float* sA1  = sA0 + 1024;               // 1024
    float* sbn1 = sA1 + 1024;               // 256
    float* sbn2 = sbn1 + 256;               // 128
    int*   sTile = (int*)(sbn2 + 128);      // 1 int

    const int tid = threadIdx.x;
    if (tid < 256) sbn1[tid] = bn1[tid];
    if (tid < 128) sbn2[tid] = bn2[tid];

    const int ig  = tid >> 5;
    const int jg  = tid & 31;
    const int n0  = ig * 8;
    const int jja = jg * 4;
    const int jjb = 128 + jg * 4;
    const int jj2 = jg * 4;
    const int an  = tid >> 2;
    const int aq  = (tid & 3) * 4;

    float csn1[8] = {0.f,0.f,0.f,0.f,0.f,0.f,0.f,0.f};
    float csn2[4] = {0.f,0.f,0.f,0.f};

    const float* g_inc1 = g_scr + OFF_INC1;
    const float* g_out1 = g_scr + OFF_OUT1;
    const float* g_inc2 = g_scr + OFF_INC2;
    const float* g_out2 = g_scr + OFF_OUT2;

    while (true) {
        if (tid == 0) *sTile = atomicAdd(&g_tick[1], 1);
        __syncthreads();
        const int tile = *sTile;
        if (tile >= K2_TILES) break;
        const int base = tile * 64;

        // ================= GEMM1: 34 chunks of 16 k, double-buffered =========
        ull acc1[8][4];
        #pragma unroll
        for (int i = 0; i < 8; i++)
            #pragma unroll
            for (int q = 0; q < 4; q++) acc1[i][q] = 0ull;

        g1_issue(0, base, sW0, sA0, Wn1, Win1, Wout1, nodes, g_inc1, g_out1, tid, an, aq);
        CPA_COMMIT();
        for (int c = 0; c < NC1; c++) {
            float* sWb = (c & 1) ? sW1 : sW0;
            float* sAb = (c & 1) ? sA1 : sA0;
            if (c + 1 < NC1) {
                g1_issue(c + 1, base, (c & 1) ? sW0 : sW1, (c & 1) ? sA0 : sA1,
                         Wn1, Win1, Wout1, nodes, g_inc1, g_out1, tid, an, aq);
                CPA_COMMIT();
                CPA_WAIT1();
            } else {
                CPA_WAIT0();
            }
            __syncthreads();
            #pragma unroll
            for (int k0 = 0; k0 < 16; k0 += 4) {
                float4 a4[8];
                #pragma unroll
                for (int i = 0; i < 8; i++)
                    a4[i] = *(const float4*)(sAb + (n0 + i) * 16 + k0);
                #pragma unroll
                for (int kk = 0; kk < 4; kk++) {
                    ulonglong2 wA = *(const ulonglong2*)(sWb + (k0 + kk) * 256 + jja);
                    ulonglong2 wB = *(const ulonglong2*)(sWb + (k0 + kk) * 256 + jjb);
                    #pragma unroll
                    for (int i = 0; i < 8; i++) {
                        float av = (kk == 0) ? a4[i].x : (kk == 1) ? a4[i].y
                                 : (kk == 2) ? a4[i].z : a4[i].w;
                        ull a = pk2(av);
                        ffma2(acc1[i][0], a, wA.x);
                        ffma2(acc1[i][1], a, wA.y);
                        ffma2(acc1[i][2], a, wB.x);
                        ffma2(acc1[i][3], a, wB.y);
                    }
                }
            }
            __syncthreads();
        }
        // epilogue: n1 -> sN1 (+colsum)
        {
            float4 b0 = *(const float4*)(sbn1 + jja);
            float4 b1 = *(const float4*)(sbn1 + jjb);
            #pragma unroll
            for (int i = 0; i < 8; i++) {
                bool valid = (base + n0 + i) < NN;
                float2 t0 = up2(acc1[i][0]), t1 = up2(acc1[i][1]);
                float2 t2 = up2(acc1[i][2]), t3 = up2(acc1[i][3]);
                float4 r0, r1;
                r0.x = valid ? fmaxf(t0.x + b0.x, 0.f) : 0.f;
                r0.y = valid ? fmaxf(t0.y + b0.y, 0.f) : 0.f;
                r0.z = valid ? fmaxf(t1.x + b0.z, 0.f) : 0.f;
                r0.w = valid ? fmaxf(t1.y + b0.w, 0.f) : 0.f;
                r1.x = valid ? fmaxf(t2.x + b1.x, 0.f) : 0.f;
                r1.y = valid ? fmaxf(t2.y + b1.y, 0.f) : 0.f;
                r1.z = valid ? fmaxf(t3.x + b1.z, 0.f) : 0.f;
                r1.w = valid ? fmaxf(t3.y + b1.w, 0.f) : 0.f;
                *(float4*)(sN1 + (n0 + i) * 256 + jja) = r0;
                *(float4*)(sN1 + (n0 + i) * 256 + jjb) = r1;
                csn1[0] += r0.x; csn1[1] += r0.y; csn1[2] += r0.z; csn1[3] += r0.w;
                csn1[4] += r1.x; csn1[5] += r1.y; csn1[6] += r1.z; csn1[7] += r1.w;
            }
        }

        // ================= GEMM2: 8 x k32 (sN1) + 16 x k16 (gather) ==========
        ull acc2[8][2];
        #pragma unroll
        for (int i = 0; i < 8; i++) { acc2[i][0] = 0ull; acc2[i][1] = 0ull; }

        g2_issue(0, base, sW0, sA0, Wn2, Win2, Wout2, g_inc2, g_out2, tid, an, aq);
        CPA_COMMIT();
        for (int c = 0; c < NC2; c++) {
            float* sWb = (c & 1) ? sW1 : sW0;
            float* sAb = (c & 1) ? sA1 : sA0;
            if (c + 1 < NC2) {
                g2_issue(c + 1, base, (c & 1) ? sW0 : sW1, (c & 1) ? sA0 : sA1,
                         Wn2, Win2, Wout2, g_inc2, g_out2, tid, an, aq);
                CPA_COMMIT();
                CPA_WAIT1();
            } else {
                CPA_WAIT0();
            }
            __syncthreads();
            if (c < 8) {
                #pragma unroll
                for (int k0 = 0; k0 < 32; k0 += 4) {
                    float4 a4[8];
                    #pragma unroll
                    for (int i = 0; i < 8; i++)
                        a4[i] = *(const float4*)(sN1 + (n0 + i) * 256 + c * 32 + k0);
                    #pragma unroll
                    for (int kk = 0; kk < 4; kk++) {
                        ulonglong2 w = *(const ulonglong2*)(sWb + (k0 + kk) * 128 + jj2);
                        #pragma unroll
                        for (int i = 0; i < 8; i++) {
                            float av = (kk == 0) ? a4[i].x : (kk == 1) ? a4[i].y
                                     : (kk == 2) ? a4[i].z : a4[i].w;
                            ull a = pk2(av);
                            ffma2(acc2[i][0], a, w.x);
                            ffma2(acc2[i][1], a, w.y);
                        }
                    }
                }
            } else {
                #pragma unroll
                for (int k0 = 0; k0 < 16; k0 += 4) {
                    float4 a4[8];
                    #pragma unroll
                    for (int i = 0; i < 8; i++)
                        a4[i] = *(const float4*)(sAb + (n0 + i) * 16 + k0);
                    #pragma unroll
                    for (int kk = 0; kk < 4; kk++) {
                        ulonglong2 w = *(const ulonglong2*)(sWb + (k0 + kk) * 128 + jj2);
                        #pragma unroll
                        for (int i = 0; i < 8; i++) {
                            float av = (kk == 0) ? a4[i].x : (kk == 1) ? a4[i].y
                                     : (kk == 2) ? a4[i].z : a4[i].w;
                            ull a = pk2(av);
                            ffma2(acc2[i][0], a, w.x);
                            ffma2(acc2[i][1], a, w.y);
                        }
                    }
                }
            }
            __syncthreads();
        }
        // epilogue: n2 -> global (+colsum)
        {
            float4 b0 = *(const float4*)(sbn2 + jj2);
            #pragma unroll
            for (int i = 0; i < 8; i++) {
                int node = base + n0 + i;
                if (node < NN) {
                    float2 t0 = up2(acc2[i][0]), t1 = up2(acc2[i][1]);
                    float4 r0;
                    r0.x = fmaxf(t0.x + b0.x, 0.f);
                    r0.y = fmaxf(t0.y + b0.y, 0.f);
                    r0.z = fmaxf(t1.x + b0.z, 0.f);
                    r0.w = fmaxf(t1.y + b0.w, 0.f);
                    *(float4*)(n2_out + (long)node * 128 + jj2) = r0;
                    csn2[0] += r0.x; csn2[1] += r0.y; csn2[2] += r0.z; csn2[3] += r0.w;
                }
            }
        }
    }
    red4(g_scr + OFF_N1SUM + jja, csn1[0], csn1[1], csn1[2], csn1[3]);
    red4(g_scr + OFF_N1SUM + jjb, csn1[4], csn1[5], csn1[6], csn1[7]);
    red4(g_scr + OFF_N2SUM + jj2, csn2[0], csn2[1], csn2[2], csn2[3]);
}

// ---------------- globals kernel ----------------
__global__ void k_glob(
    const float* __restrict__ gu,
    const float* __restrict__ Wu1, const float* __restrict__ Wgn1,
    const float* __restrict__ Wge1, const float* __restrict__ bu1,
    const float* __restrict__ Wu2, const float* __restrict__ Wgn2,
    const float* __restrict__ Wge2, const float* __restrict__ bu2,
    float* __restrict__ u2_out)
{
    __shared__ float su1[256];
    __shared__ float sgu[16];
    __shared__ float sn1m[256], se1m[256];
    const int tid = threadIdx.x;
    if (tid < 16) sgu[tid] = gu[tid];
    sn1m[tid] = g_scr[OFF_N1SUM + tid] * (1.0f / NN);
    se1m[tid] = g_scr[OFF_E1SUM + tid] * (1.0f / EE);
    __syncthreads();
    {
        float s = bu1[tid];
        #pragma unroll 4
        for (int k = 0; k < 16; k++) s = fmaf(sgu[k], Wu1[k * 256 + tid], s);
        #pragma unroll 4
        for (int k = 0; k < 256; k++) {
            s = fmaf(sn1m[k], Wgn1[k * 256 + tid], s);
            s = fmaf(se1m[k], Wge1[k * 256 + tid], s);
        }
        su1[tid] = fmaxf(s, 0.f);
    }
    __syncthreads();
    if (tid < 128) {
        float s = bu2[tid];
        #pragma unroll 4
        for (int k = 0; k < 256; k++) s = fmaf(su1[k], Wu2[k * 128 + tid], s);
        #pragma unroll 4
        for (int k = 0; k < 128; k++) {
            s = fmaf(g_scr[OFF_N2SUM + k] * (1.0f / NN), Wgn2[k * 128 + tid], s);
            s = fmaf(g_scr[OFF_E2SUM + k] * (1.0f / EE), Wge2[k * 128 + tid], s);
        }
        u2_out[tid] = fmaxf(s, 0.f);
    }
}

extern "C" void kernel_launch(void* const* d_in, const int* in_sizes, int n_in,
                              void* d_out, int out_size) {
    const float* nodes = (const float*)d_in[0];
    const float* edges = (const float*)d_in[1];
    const float* gu    = (const float*)d_in[2];
    const int*   snd   = (const int*)d_in[3];
    const int*   rcv   = (const int*)d_in[4];
    const float* We1 = (const float*)d_in[5];
    const float* be1 = (const float*)d_in[6];
    const float* Wn1 = (const float*)d_in[7];
    const float* Win1 = (const float*)d_in[8];
    const float* Wout1 = (const float*)d_in[9];
    const float* bn1 = (const float*)d_in[10];
    const float* Wu1 = (const float*)d_in[11];
    const float* Wgn1 = (const float*)d_in[12];
    const float* Wge1 = (const float*)d_in[13];
    const float* bu1 = (const float*)d_in[14];
    const float* We2 = (const float*)d_in[15];
    const float* be2 = (const float*)d_in[16];
    const float* Wn2 = (const float*)d_in[17];
    const float* Win2 = (const float*)d_in[18];
    const float* Wout2 = (const float*)d_in[19];
    const float* bn2 = (const float*)d_in[20];
    const float* Wu2 = (const float*)d_in[21];
    const float* Wgn2 = (const float*)d_in[22];
    const float* Wge2 = (const float*)d_in[23];
    const float* bu2 = (const float*)d_in[24];

    float* out    = (float*)d_out;
    float* n2_out = out;
    float* e2_out = out + (long)NN * H2;                       // 6,400,000
    float* u2_out = out + (long)NN * H2 + (long)EE * H2;       // 57,600,000

    const int SMEM_K1 = (32768 + 4096 + 12288 + 1536 + 256 + 128) * 4;   // 204288
    const int SMEM_K2 = (16384 + 4096 + 4096 + 1024 + 1024 + 256 + 128 + 4) * 4; // 108048
    cudaFuncSetAttribute(k_edges, cudaFuncAttributeMaxDynamicSharedMemorySize, SMEM_K1);
    cudaFuncSetAttribute(k_nodes, cudaFuncAttributeMaxDynamicSharedMemorySize, SMEM_K2);

    k_zero<<<(ZERO_FLOATS / 4 + 255) / 256, 256>>>();
    k_deg<<<(EE + 255) / 256, 256>>>(snd, rcv);
    k_inv<<<(NN + 255) / 256, 256>>>();
    k_edges<<<148, NT, SMEM_K1>>>(edges, snd, rcv, We1, be1, We2, be2, e2_out);
    k_nodes<<<296, 256, SMEM_K2>>>(nodes, Wn1, Win1, Wout1, bn1,
                                   Wn2, Win2, Wout2, bn2, n2_out);
    k_glob<<<1, 256>>>(gu, Wu1, Wgn1, Wge1, bu1, Wu2, Wgn2, Wge2, bu2, u2_out);
}